// round 13
// baseline (speedup 1.0000x reference)
#include <cuda_runtime.h>
#include <cuda_bf16.h>
#include <math.h>
#include <stdint.h>

// ---------------------------------------------------------------------------
// changeAttention on GB300 (plain sm_103 -> mma.sync HMMA).
// bf16x3 split grouped GEMMs + bf16x3 HMMA attention (bit-packed mask),
// with convln + mask-pack forked onto side streams in the capture graph.
//   B=8, N=1024, C=512, heads=8, d=64, r=128, SR=2 -> Nn=256
// ---------------------------------------------------------------------------

#define NB    8
#define NTOK  1024
#define CDIM  512
#define NHEAD 8
#define HD    64
#define RLOW  128
#define NKV   256
#define MROW  (NB * NTOK)   // 8192
#define MKV   (NB * NKV)    // 2048

typedef __nv_bfloat16 bf16;

// ---------------- scratch (device globals) ----------------
__device__ __align__(128) bf16 g_xh  [MROW * CDIM],      g_xl  [MROW * CDIM];
__device__ __align__(128) bf16 g_qw1h[RLOW * CDIM],      g_qw1l[RLOW * CDIM];
__device__ __align__(128) bf16 g_kvw1h[2 * RLOW * CDIM], g_kvw1l[2 * RLOW * CDIM];
__device__ __align__(128) bf16 g_qw2h[CDIM * RLOW],      g_qw2l[CDIM * RLOW];
__device__ __align__(128) bf16 g_kw2h[CDIM * RLOW],      g_kw2l[CDIM * RLOW];
__device__ __align__(128) bf16 g_vw2h[CDIM * RLOW],      g_vw2l[CDIM * RLOW];
__device__ __align__(128) bf16 g_pwh [CDIM * CDIM],      g_pwl [CDIM * CDIM];
__device__ __align__(128) bf16 g_qlh [MROW * RLOW],      g_qll [MROW * RLOW];
__device__ __align__(128) bf16 g_xsh [MKV  * CDIM],      g_xsl [MKV  * CDIM];
__device__ __align__(128) bf16 g_kvlh[MKV * 2 * RLOW],   g_kvll[MKV * 2 * RLOW];
__device__ __align__(128) bf16 g_q2h [MROW * CDIM],      g_q2l [MROW * CDIM];
__device__ __align__(128) bf16 g_k2h [MKV  * CDIM],      g_k2l [MKV  * CDIM];
__device__ __align__(128) bf16 g_vth [MKV  * CDIM],      g_vtl [MKV  * CDIM];  // (b,c,m)
__device__ __align__(128) bf16 g_aoh [MROW * CDIM],      g_aol [MROW * CDIM];
__device__ __align__(128) uint32_t g_maskp[NB * NHEAD * NTOK * (NKV / 32)];    // 2 MB

// ---------------- PTX helpers ----------------
__device__ __forceinline__ uint32_t smem_u32(const void* p) {
    uint32_t a;
    asm("{ .reg .u64 t; cvta.to.shared.u64 t, %1; cvt.u32.u64 %0, t; }" : "=r"(a) : "l"(p));
    return a;
}
#define CP16(d, s)   asm volatile("cp.async.ca.shared.global [%0], [%1], 16;" :: "r"(d), "l"(s))
#define CP_COMMIT()  asm volatile("cp.async.commit_group;" ::: "memory")
#define CP_WAIT1()   asm volatile("cp.async.wait_group 1;" ::: "memory")
#define CP_WAIT0()   asm volatile("cp.async.wait_group 0;" ::: "memory")

#define LDMX4(r, addr)                                                         \
    asm volatile("ldmatrix.sync.aligned.m8n8.x4.shared.b16 {%0,%1,%2,%3}, [%4];" \
        : "=r"((r)[0]), "=r"((r)[1]), "=r"((r)[2]), "=r"((r)[3]) : "r"(addr))

#define MMA(d, a, b0, b1)                                                      \
    asm volatile("mma.sync.aligned.m16n8k16.row.col.f32.bf16.bf16.f32 "        \
        "{%0,%1,%2,%3},{%4,%5,%6,%7},{%8,%9},{%0,%1,%2,%3};"                   \
        : "+f"((d)[0]), "+f"((d)[1]), "+f"((d)[2]), "+f"((d)[3])               \
        : "r"((a)[0]), "r"((a)[1]), "r"((a)[2]), "r"((a)[3]), "r"(b0), "r"(b1))

__device__ __forceinline__ void pack_hl(float a, float b, uint32_t& h, uint32_t& l) {
    __nv_bfloat162 hh = __floats2bfloat162_rn(a, b);
    h = *reinterpret_cast<uint32_t*>(&hh);
    __nv_bfloat162 ll = __floats2bfloat162_rn(a - __bfloat162float(hh.x),
                                              b - __bfloat162float(hh.y));
    l = *reinterpret_cast<uint32_t*>(&ll);
}

// ---------------------------------------------------------------------------
// Grouped bf16x3 GEMM: up to 3 problems per launch, linear CTA decode.
// ---------------------------------------------------------------------------
#define TROWS 40

struct GemmGroup {
    int base1, base2;
    int gx[3];
    const bf16 *Ah[3], *Al[3], *Bh[3], *Bl[3];
    bf16 *Chi[3], *Clo[3], *Vth[3], *Vtl[3];
    float *C[3];
    const float *bias[3];
    int lda[3], N[3], K[3];
};

template<int NMI>
__device__ __forceinline__ void stage_loadT(
    const bf16* __restrict__ Ah, const bf16* __restrict__ Al, int lda,
    const bf16* __restrict__ Bh, const bf16* __restrict__ Bl,
    int m0, int n0, int K, int k0, uint32_t st, int tid)
{
    constexpr int ATB = 64 * NMI * TROWS * 2;
    constexpr int BTB = 128 * TROWS * 2;
    const bf16* a0 = Ah + (size_t)m0 * lda + k0;
    const bf16* a1 = Al + (size_t)m0 * lda + k0;
    const bf16* b0 = Bh + (size_t)n0 * K + k0;
    const bf16* b1 = Bl + (size_t)n0 * K + k0;
#pragma unroll
    for (int i = tid; i < 64 * NMI * 4; i += 256) {
        int r = i >> 2, c = i & 3;
        CP16(st + r * 80 + c * 16,       a0 + (size_t)r * lda + c * 8);
        CP16(st + ATB + r * 80 + c * 16, a1 + (size_t)r * lda + c * 8);
    }
#pragma unroll
    for (int i = tid; i < 512; i += 256) {
        int r = i >> 2, c = i & 3;
        CP16(st + 2 * ATB + r * 80 + c * 16,       b0 + (size_t)r * K + c * 8);
        CP16(st + 2 * ATB + BTB + r * 80 + c * 16, b1 + (size_t)r * K + c * 8);
    }
}

__device__ __forceinline__ uint32_t frag_addr(uint32_t tile, int row0, int kstep, int lane) {
    return tile + ((row0 + (lane & 15)) * TROWS + kstep * 16 + (lane >> 4) * 8) * 2;
}

template<int NMI>
__global__ void __launch_bounds__(256, 2) gemm3g_kernel(GemmGroup g)
{
    constexpr int ATB = 64 * NMI * TROWS * 2;
    constexpr int BTB = 128 * TROWS * 2;
    constexpr int STB = 2 * ATB + 2 * BTB;
    extern __shared__ char smem[];
    const uint32_t sb = smem_u32(smem);
    const int tid = threadIdx.x, lane = tid & 31, wid = tid >> 5;
    const int warp_m = wid >> 1, warp_n = wid & 1;

    const int cta = blockIdx.x;
    const int p = (cta >= g.base1) + (cta >= g.base2);
    const int local = cta - (p == 2 ? g.base2 : (p == 1 ? g.base1 : 0));
    const int gx = g.gx[p];
    const int m0 = (local / gx) * (64 * NMI), n0 = (local % gx) * 128;
    const bf16 *Ah = g.Ah[p], *Al = g.Al[p], *Bh = g.Bh[p], *Bl = g.Bl[p];
    const int lda = g.lda[p], N = g.N[p], K = g.K[p];
    const int nch = K >> 5;

    float acc[NMI][8][4];
#pragma unroll
    for (int i = 0; i < NMI; i++)
#pragma unroll
        for (int j = 0; j < 8; j++)
#pragma unroll
            for (int t = 0; t < 4; t++) acc[i][j][t] = 0.f;

    stage_loadT<NMI>(Ah, Al, lda, Bh, Bl, m0, n0, K, 0, sb, tid);
    CP_COMMIT();

    for (int ch = 0; ch < nch; ch++) {
        if (ch + 1 < nch) {
            stage_loadT<NMI>(Ah, Al, lda, Bh, Bl, m0, n0, K, (ch + 1) << 5,
                             sb + ((ch + 1) & 1) * STB, tid);
            CP_COMMIT();
            CP_WAIT1();
        } else {
            CP_WAIT0();
        }
        __syncthreads();

        const uint32_t st = sb + (ch & 1) * STB;
#pragma unroll
        for (int ks = 0; ks < 2; ks++) {
            uint32_t ah[NMI][4], al[NMI][4], bh[4][4], bl[4][4];
#pragma unroll
            for (int mi = 0; mi < NMI; mi++) {
                LDMX4(ah[mi], frag_addr(st,       warp_m * 16 * NMI + mi * 16, ks, lane));
                LDMX4(al[mi], frag_addr(st + ATB, warp_m * 16 * NMI + mi * 16, ks, lane));
            }
#pragma unroll
            for (int q = 0; q < 4; q++) {
                LDMX4(bh[q], frag_addr(st + 2 * ATB,       warp_n * 64 + q * 16, ks, lane));
                LDMX4(bl[q], frag_addr(st + 2 * ATB + BTB, warp_n * 64 + q * 16, ks, lane));
            }
#pragma unroll
            for (int mi = 0; mi < NMI; mi++)
#pragma unroll
                for (int q = 0; q < 4; q++) {
                    MMA(acc[mi][2 * q],     ah[mi], bh[q][0], bh[q][2]);
                    MMA(acc[mi][2 * q + 1], ah[mi], bh[q][1], bh[q][3]);
                    MMA(acc[mi][2 * q],     ah[mi], bl[q][0], bl[q][2]);
                    MMA(acc[mi][2 * q + 1], ah[mi], bl[q][1], bl[q][3]);
                    MMA(acc[mi][2 * q],     al[mi], bh[q][0], bh[q][2]);
                    MMA(acc[mi][2 * q + 1], al[mi], bh[q][1], bh[q][3]);
                }
        }
        __syncthreads();
    }

    float* C = g.C[p];
    bf16 *Chi = g.Chi[p], *Clo = g.Clo[p], *Vth = g.Vth[p], *Vtl = g.Vtl[p];
    const float* bias = g.bias[p];
    const int gr = lane >> 2, c2 = (lane & 3) * 2;
#pragma unroll
    for (int mi = 0; mi < NMI; mi++)
#pragma unroll
        for (int hh = 0; hh < 2; hh++) {
            const int row = m0 + warp_m * 16 * NMI + mi * 16 + hh * 8 + gr;
#pragma unroll
            for (int ni = 0; ni < 8; ni++) {
                const int col = n0 + warp_n * 64 + ni * 8 + c2;
                float v0 = acc[mi][ni][hh * 2 + 0];
                float v1 = acc[mi][ni][hh * 2 + 1];
                if (bias) { v0 += bias[col]; v1 += bias[col + 1]; }
                const size_t off = (size_t)row * N + col;
                if (C) *(float2*)(C + off) = make_float2(v0, v1);
                if (Chi || Vth) {
                    bf16 h0 = __float2bfloat16(v0), h1 = __float2bfloat16(v1);
                    bf16 l0 = __float2bfloat16(v0 - __bfloat162float(h0));
                    bf16 l1 = __float2bfloat16(v1 - __bfloat162float(h1));
                    if (Chi) {
                        *(__nv_bfloat162*)(Chi + off) = __nv_bfloat162(h0, h1);
                        *(__nv_bfloat162*)(Clo + off) = __nv_bfloat162(l0, l1);
                    }
                    if (Vth) {  // transposed (b, c, m) layout
                        size_t toff = ((size_t)((row >> 8) * CDIM + col)) * NKV + (row & 255);
                        Vth[toff] = h0; Vth[toff + NKV] = h1;
                        Vtl[toff] = l0; Vtl[toff + NKV] = l1;
                    }
                }
            }
        }
}

// ---------------- fp32 -> (bf16 hi, bf16 lo) splits (one launch) ----------------
__device__ __forceinline__ void split4(const float* __restrict__ s, bf16* __restrict__ h,
                                       bf16* __restrict__ l, int i) {
    float4 v = ((const float4*)s)[i];
    bf16 h0 = __float2bfloat16(v.x), h1 = __float2bfloat16(v.y);
    bf16 h2 = __float2bfloat16(v.z), h3 = __float2bfloat16(v.w);
    ((__nv_bfloat162*)h)[i * 2 + 0] = __nv_bfloat162(h0, h1);
    ((__nv_bfloat162*)h)[i * 2 + 1] = __nv_bfloat162(h2, h3);
    ((__nv_bfloat162*)l)[i * 2 + 0] = __nv_bfloat162(
        __float2bfloat16(v.x - __bfloat162float(h0)),
        __float2bfloat16(v.y - __bfloat162float(h1)));
    ((__nv_bfloat162*)l)[i * 2 + 1] = __nv_bfloat162(
        __float2bfloat16(v.z - __bfloat162float(h2)),
        __float2bfloat16(v.w - __bfloat162float(h3)));
}

#define XN4 (MROW * CDIM / 4)        // 1048576
#define WN4 16384                    // RLOW*CDIM/4
#define PN4 (CDIM * CDIM / 4)        // 65536
#define SPLIT_TOT (XN4 + 6 * WN4 + PN4)

__global__ void split_all_kernel(
    const float* __restrict__ x,
    const float* __restrict__ qw1, const float* __restrict__ kw1,
    const float* __restrict__ vw1, const float* __restrict__ qw2,
    const float* __restrict__ kw2, const float* __restrict__ vw2,
    const float* __restrict__ pw,
    bf16* __restrict__ xh, bf16* __restrict__ xl,
    bf16* __restrict__ qw1h, bf16* __restrict__ qw1l,
    bf16* __restrict__ kvw1h, bf16* __restrict__ kvw1l,
    bf16* __restrict__ qw2h, bf16* __restrict__ qw2l,
    bf16* __restrict__ kw2h, bf16* __restrict__ kw2l,
    bf16* __restrict__ vw2h, bf16* __restrict__ vw2l,
    bf16* __restrict__ pwh, bf16* __restrict__ pwl)
{
    int i = blockIdx.x * blockDim.x + threadIdx.x;
    if (i < XN4) { split4(x, xh, xl, i); return; }
    i -= XN4;
    if (i < 6 * WN4) {
        int j = i / WN4, off = i - j * WN4;
        switch (j) {
            case 0: split4(qw1, qw1h, qw1l, off); break;
            case 1: split4(kw1, kvw1h, kvw1l, off); break;
            case 2: split4(vw1, kvw1h + 4 * WN4, kvw1l + 4 * WN4, off); break;
            case 3: split4(qw2, qw2h, qw2l, off); break;
            case 4: split4(kw2, kw2h, kw2l, off); break;
            default: split4(vw2, vw2h, vw2l, off); break;
        }
    } else {
        int off = i - 6 * WN4;
        if (off < PN4) split4(pw, pwh, pwl, off);
    }
}

// ---------------- mask int32 -> bit-packed (ballot, coalesced) ----------------
__global__ void pack_mask_kernel(const int* __restrict__ m, uint32_t* __restrict__ o) {
    int idx = blockIdx.x * blockDim.x + threadIdx.x;
    uint32_t b = __ballot_sync(0xffffffffu, m[idx] != 0);
    if ((threadIdx.x & 31) == 0) o[idx >> 5] = b;
}

// ---------------------------------------------------------------------------
// Depthwise 2x2/s2 conv + bias + LayerNorm(C); writes bf16 (hi,lo) split.
// ---------------------------------------------------------------------------
__global__ void convln_kernel(const float* __restrict__ x, const float* __restrict__ sr_w,
                              const float* __restrict__ sr_b, const float* __restrict__ ln_g,
                              const float* __restrict__ ln_b,
                              bf16* __restrict__ xsh, bf16* __restrict__ xsl) {
    const int b = blockIdx.x >> 8, n = blockIdx.x & 255;
    const int ph = n >> 4, pw = n & 15, c = threadIdx.x;
    const float* xb = x + (size_t)b * NTOK * CDIM;
    const int r0 = ph * 64 + pw * 2;

    float val = xb[(size_t)(r0)      * CDIM + c] * sr_w[c * 4 + 0]
              + xb[(size_t)(r0 + 1)  * CDIM + c] * sr_w[c * 4 + 1]
              + xb[(size_t)(r0 + 32) * CDIM + c] * sr_w[c * 4 + 2]
              + xb[(size_t)(r0 + 33) * CDIM + c] * sr_w[c * 4 + 3]
              + sr_b[c];

    float s1 = val, s2 = val * val;
#pragma unroll
    for (int o = 16; o > 0; o >>= 1) {
        s1 += __shfl_xor_sync(0xffffffffu, s1, o);
        s2 += __shfl_xor_sync(0xffffffffu, s2, o);
    }
    __shared__ float r1[16], r2[16];
    const int w = c >> 5, lane = c & 31;
    if (lane == 0) { r1[w] = s1; r2[w] = s2; }
    __syncthreads();
    float t1 = 0.f, t2 = 0.f;
#pragma unroll
    for (int i = 0; i < 16; i++) { t1 += r1[i]; t2 += r2[i]; }
    const float mu  = t1 * (1.f / 512.f);
    const float var = t2 * (1.f / 512.f) - mu * mu;
    const float inv = rsqrtf(var + 1e-5f);
    const float o = (val - mu) * inv * ln_g[c] + ln_b[c];
    const size_t off = (size_t)(b * NKV + n) * CDIM + c;
    bf16 h = __float2bfloat16(o);
    xsh[off] = h;
    xsl[off] = __float2bfloat16(o - __bfloat162float(h));
}

// ---------------------------------------------------------------------------
// HMMA attention: CTA = (b, h, 512 q rows as 4 subtiles of 128). 8 warps.
// K/V staged once; Q double-buffered; mask read as packed bits (8 words/row).
// ---------------------------------------------------------------------------
#define AQS 72
#define AKS 72
#define AVS 264
#define QBUF(i) ((i) * 36864)
#define KH_OFF 73728
#define KL_OFF 110592
#define VH_OFF 147456
#define VL_OFF 181248
#define ATTN_SMEM 215040

__global__ void __launch_bounds__(256, 1) attn_kernel(
    const bf16* __restrict__ qh, const bf16* __restrict__ ql,
    const bf16* __restrict__ kh, const bf16* __restrict__ kl,
    const bf16* __restrict__ vth, const bf16* __restrict__ vtl,
    const uint32_t* __restrict__ maskp,
    bf16* __restrict__ aoh, bf16* __restrict__ aol)
{
    extern __shared__ char smem[];
    const uint32_t sb = smem_u32(smem);
    const int qt = blockIdx.x;          // 0..1 (512 q rows each)
    const int bh = blockIdx.y;          // 0..63
    const int b = bh >> 3, h = bh & 7;
    const int tid = threadIdx.x, lane = tid & 31, wid = tid >> 5;

    const bf16* khg = kh + ((size_t)(b * NKV)) * CDIM + h * HD;
    const bf16* klg = kl + ((size_t)(b * NKV)) * CDIM + h * HD;
    const bf16* vhg = vth + ((size_t)(b * CDIM + h * HD)) * NKV;
    const bf16* vlg = vtl + ((size_t)(b * CDIM + h * HD)) * NKV;
    const bf16* qhg0 = qh + ((size_t)(b * NTOK + qt * 512)) * CDIM + h * HD;
    const bf16* qlg0 = ql + ((size_t)(b * NTOK + qt * 512)) * CDIM + h * HD;

    // stage K (256x64), Vt (64x256), Q subtile 0
#pragma unroll
    for (int i = tid; i < 2048; i += 256) {
        int r = i >> 3, c = i & 7;
        CP16(sb + KH_OFF + r * (AKS * 2) + c * 16, khg + (size_t)r * CDIM + c * 8);
        CP16(sb + KL_OFF + r * (AKS * 2) + c * 16, klg + (size_t)r * CDIM + c * 8);
    }
#pragma unroll
    for (int i = tid; i < 2048; i += 256) {
        int r = i >> 5, c = i & 31;
        CP16(sb + VH_OFF + r * (AVS * 2) + c * 16, vhg + (size_t)r * NKV + c * 8);
        CP16(sb + VL_OFF + r * (AVS * 2) + c * 16, vlg + (size_t)r * NKV + c * 8);
    }
#pragma unroll
    for (int i = tid; i < 1024; i += 256) {
        int r = i >> 3, c = i & 7;
        CP16(sb + QBUF(0) + r * (AQS * 2) + c * 16,         qhg0 + (size_t)r * CDIM + c * 8);
        CP16(sb + QBUF(0) + 18432 + r * (AQS * 2) + c * 16, qlg0 + (size_t)r * CDIM + c * 8);
    }
    CP_COMMIT();

    const int row0 = wid * 16;
    const int gr = lane >> 2, cq = (lane & 3) * 2;
    const float scale = 0.125f;

    for (int s = 0; s < 4; s++) {
        CP_WAIT0();
        __syncthreads();
        const uint32_t qb = sb + QBUF(s & 1);
        const int qrow0 = qt * 512 + s * 128;

        float acc[32][4];
#pragma unroll
        for (int na = 0; na < 32; na++)
#pragma unroll
            for (int t = 0; t < 4; t++) acc[na][t] = 0.f;

#pragma unroll
        for (int ks = 0; ks < 4; ks++) {
            uint32_t a_h[4], a_l[4];
            LDMX4(a_h, qb + ((row0 + (lane & 15)) * AQS + ks * 16 + (lane >> 4) * 8) * 2);
            LDMX4(a_l, qb + 18432 + ((row0 + (lane & 15)) * AQS + ks * 16 + (lane >> 4) * 8) * 2);
#pragma unroll
            for (int nb = 0; nb < 16; nb++) {
                uint32_t k_h[4], k_l[4];
                LDMX4(k_h, sb + KH_OFF + ((nb * 16 + (lane & 15)) * AKS + ks * 16 + (lane >> 4) * 8) * 2);
                LDMX4(k_l, sb + KL_OFF + ((nb * 16 + (lane & 15)) * AKS + ks * 16 + (lane >> 4) * 8) * 2);
                MMA(acc[2 * nb],     a_h, k_h[0], k_h[2]);
                MMA(acc[2 * nb + 1], a_h, k_h[1], k_h[3]);
                MMA(acc[2 * nb],     a_h, k_l[0], k_l[2]);
                MMA(acc[2 * nb + 1], a_h, k_l[1], k_l[3]);
                MMA(acc[2 * nb],     a_l, k_h[0], k_h[2]);
                MMA(acc[2 * nb + 1], a_l, k_h[1], k_h[3]);
            }
        }

        // prefetch next Q subtile into other buffer (overlaps softmax + PV)
        if (s < 3) {
            const bf16* nqh = qhg0 + (size_t)(s + 1) * 128 * CDIM;
            const bf16* nql = qlg0 + (size_t)(s + 1) * 128 * CDIM;
            const uint32_t nqb = sb + QBUF((s + 1) & 1);
#pragma unroll
            for (int i = tid; i < 1024; i += 256) {
                int r = i >> 3, c = i & 7;
                CP16(nqb + r * (AQS * 2) + c * 16,         nqh + (size_t)r * CDIM + c * 8);
                CP16(nqb + 18432 + r * (AQS * 2) + c * 16, nql + (size_t)r * CDIM + c * 8);
            }
            CP_COMMIT();
        }

        // packed mask: 8 words per row; col c -> word c>>5, bit c&31
        const uint32_t* mp0 = maskp + ((size_t)bh * NTOK + qrow0 + row0 + gr) * 8;
        uint32_t w0[8], w1[8];
        *(uint4*)(w0)     = *(const uint4*)(mp0);
        *(uint4*)(w0 + 4) = *(const uint4*)(mp0 + 4);
        *(uint4*)(w1)     = *(const uint4*)(mp0 + 64);
        *(uint4*)(w1 + 4) = *(const uint4*)(mp0 + 68);

        float mx0 = -1e30f, mx1 = -1e30f;
#pragma unroll
        for (int na = 0; na < 32; na++) {
            const int wrd = na >> 2, bb = ((na & 3) << 3) | cq;
            float s0 = acc[na][0] * scale; if ((w0[wrd] >> bb) & 1)       s0 = -1e30f;
            float s1 = acc[na][1] * scale; if ((w0[wrd] >> (bb + 1)) & 1) s1 = -1e30f;
            float s2 = acc[na][2] * scale; if ((w1[wrd] >> bb) & 1)       s2 = -1e30f;
            float s3 = acc[na][3] * scale; if ((w1[wrd] >> (bb + 1)) & 1) s3 = -1e30f;
            acc[na][0] = s0; acc[na][1] = s1; acc[na][2] = s2; acc[na][3] = s3;
            mx0 = fmaxf(mx0, fmaxf(s0, s1));
            mx1 = fmaxf(mx1, fmaxf(s2, s3));
        }
        mx0 = fmaxf(mx0, __shfl_xor_sync(0xffffffffu, mx0, 1));
        mx0 = fmaxf(mx0, __shfl_xor_sync(0xffffffffu, mx0, 2));
        mx1 = fmaxf(mx1, __shfl_xor_sync(0xffffffffu, mx1, 1));
        mx1 = fmaxf(mx1, __shfl_xor_sync(0xffffffffu, mx1, 2));

        float sum0 = 0.f, sum1 = 0.f;
#pragma unroll
        for (int na = 0; na < 32; na++) {
            float e0 = __expf(acc[na][0] - mx0);
            float e1 = __expf(acc[na][1] - mx0);
            float e2 = __expf(acc[na][2] - mx1);
            float e3 = __expf(acc[na][3] - mx1);
            acc[na][0] = e0; acc[na][1] = e1; acc[na][2] = e2; acc[na][3] = e3;
            sum0 += e0 + e1; sum1 += e2 + e3;
        }
        sum0 += __shfl_xor_sync(0xffffffffu, sum0, 1);
        sum0 += __shfl_xor_sync(0xffffffffu, sum0, 2);
        sum1 += __shfl_xor_sync(0xffffffffu, sum1, 1);
        sum1 += __shfl_xor_sync(0xffffffffu, sum1, 2);

        float acco[8][4];
#pragma unroll
        for (int na = 0; na < 8; na++)
#pragma unroll
            for (int t = 0; t < 4; t++) acco[na][t] = 0.f;

#pragma unroll
        for (int t = 0; t < 16; t++) {
            uint32_t p_h[4], p_l[4];
            pack_hl(acc[2 * t][0],     acc[2 * t][1],     p_h[0], p_l[0]);
            pack_hl(acc[2 * t][2],     acc[2 * t][3],     p_h[1], p_l[1]);
            pack_hl(acc[2 * t + 1][0], acc[2 * t + 1][1], p_h[2], p_l[2]);
            pack_hl(acc[2 * t + 1][2], acc[2 * t + 1][3], p_h[3], p_l[3]);
#pragma unroll
            for (int vb = 0; vb < 4; vb++) {
                uint32_t v_h[4], v_l[4];
                LDMX4(v_h, sb + VH_OFF + ((vb * 16 + (lane & 15)) * AVS + t * 16 + (lane >> 4) * 8) * 2);
                LDMX4(v_l, sb + VL_OFF + ((vb * 16 + (lane & 15)) * AVS + t * 16 + (lane >> 4) * 8) * 2);
                MMA(acco[2 * vb],     p_h, v_h[0], v_h[2]);
                MMA(acco[2 * vb + 1], p_h, v_h[1], v_h[3]);
                MMA(acco[2 * vb],     p_h, v_l[0], v_l[2]);
                MMA(acco[2 * vb + 1], p_h, v_l[1], v_l[3]);
                MMA(acco[2 * vb],     p_l, v_h[0], v_h[2]);
                MMA(acco[2 * vb + 1], p_l, v_h[1], v_h[3]);
            }
        }

        const float i0 = 1.f / sum0, i1 = 1.f / sum1;
        const size_t rbase = ((size_t)(b * NTOK + qrow0 + row0 + gr)) * CDIM + h * HD;
#pragma unroll
        for (int na = 0; na < 8; na++) {
            const int c = na * 8 + cq;
            uint32_t h0, l0, h1, l1;
            pack_hl(acco[na][0] * i0, acco[na][1] * i0, h0, l0);
            pack_hl(acco[na][2] * i1, acco[na][3] * i1, h1, l1);
            *(uint32_t*)(aoh + rbase + c)            = h0;
            *(uint32_t*)(aol + rbase + c)            = l0;
            *(uint32_t*)(aoh + rbase + 8 * CDIM + c) = h1;
            *(uint32_t*)(aol + rbase + 8 * CDIM + c) = l1;
        }
    }
}

// ---------------------------------------------------------------------------
extern "C" void kernel_launch(void* const* d_in, const int* in_sizes, int n_in,
                              void* d_out, int out_size) {
    const float* x      = (const float*)d_in[0];
    const int*   mask   = (const int*)d_in[1];
    const float* q_w1   = (const float*)d_in[2];
    const float* q_w2   = (const float*)d_in[3];
    const float* k_w1   = (const float*)d_in[4];
    const float* k_w2   = (const float*)d_in[5];
    const float* v_w1   = (const float*)d_in[6];
    const float* v_w2   = (const float*)d_in[7];
    const float* sr_w   = (const float*)d_in[8];
    const float* sr_b   = (const float*)d_in[9];
    const float* ln_g   = (const float*)d_in[10];
    const float* ln_b   = (const float*)d_in[11];
    const float* proj_w = (const float*)d_in[12];
    const float* proj_b = (const float*)d_in[13];
    float* out = (float*)d_out;

    bf16 *xh, *xl, *qw1h, *qw1l, *kvw1h, *kvw1l;
    bf16 *qw2h, *qw2l, *kw2h, *kw2l, *vw2h, *vw2l, *pwh, *pwl;
    bf16 *qlh, *qll, *xsh, *xsl, *kvlh, *kvll;
    bf16 *q2h, *q2l, *k2h, *k2l, *vth, *vtl, *aoh, *aol;
    uint32_t* maskp;
    cudaGetSymbolAddress((void**)&xh, g_xh);       cudaGetSymbolAddress((void**)&xl, g_xl);
    cudaGetSymbolAddress((void**)&qw1h, g_qw1h);   cudaGetSymbolAddress((void**)&qw1l, g_qw1l);
    cudaGetSymbolAddress((void**)&kvw1h, g_kvw1h); cudaGetSymbolAddress((void**)&kvw1l, g_kvw1l);
    cudaGetSymbolAddress((void**)&qw2h, g_qw2h);   cudaGetSymbolAddress((void**)&qw2l, g_qw2l);
    cudaGetSymbolAddress((void**)&kw2h, g_kw2h);   cudaGetSymbolAddress((void**)&kw2l, g_kw2l);
    cudaGetSymbolAddress((void**)&vw2h, g_vw2h);   cudaGetSymbolAddress((void**)&vw2l, g_vw2l);
    cudaGetSymbolAddress((void**)&pwh, g_pwh);     cudaGetSymbolAddress((void**)&pwl, g_pwl);
    cudaGetSymbolAddress((void**)&qlh, g_qlh);     cudaGetSymbolAddress((void**)&qll, g_qll);
    cudaGetSymbolAddress((void**)&xsh, g_xsh);     cudaGetSymbolAddress((void**)&xsl, g_xsl);
    cudaGetSymbolAddress((void**)&kvlh, g_kvlh);   cudaGetSymbolAddress((void**)&kvll, g_kvll);
    cudaGetSymbolAddress((void**)&q2h, g_q2h);     cudaGetSymbolAddress((void**)&q2l, g_q2l);
    cudaGetSymbolAddress((void**)&k2h, g_k2h);     cudaGetSymbolAddress((void**)&k2l, g_k2l);
    cudaGetSymbolAddress((void**)&vth, g_vth);     cudaGetSymbolAddress((void**)&vtl, g_vtl);
    cudaGetSymbolAddress((void**)&aoh, g_aoh);     cudaGetSymbolAddress((void**)&aol, g_aol);
    cudaGetSymbolAddress((void**)&maskp, g_maskp);

    constexpr int SM1 = 2 * (2 * (64 * TROWS * 2) + 2 * (128 * TROWS * 2));   // 61440
    constexpr int SM2 = 2 * (2 * (128 * TROWS * 2) + 2 * (128 * TROWS * 2));  // 81920

    static cudaStream_t sA = nullptr, sB = nullptr;
    static cudaEvent_t ef0 = nullptr, ef1 = nullptr, eA = nullptr, eB = nullptr;
    static bool cfg = false;
    if (!cfg) {
        cudaFuncSetAttribute(gemm3g_kernel<1>, cudaFuncAttributeMaxDynamicSharedMemorySize, SM1);
        cudaFuncSetAttribute(gemm3g_kernel<2>, cudaFuncAttributeMaxDynamicSharedMemorySize, SM2);
        cudaFuncSetAttribute(attn_kernel, cudaFuncAttributeMaxDynamicSharedMemorySize, ATTN_SMEM);
        cudaStreamCreateWithFlags(&sA, cudaStreamNonBlocking);
        cudaStreamCreateWithFlags(&sB, cudaStreamNonBlocking);
        cudaEventCreateWithFlags(&ef0, cudaEventDisableTiming);
        cudaEventCreateWithFlags(&ef1, cudaEventDisableTiming);
        cudaEventCreateWithFlags(&eA, cudaEventDisableTiming);
        cudaEventCreateWithFlags(&eB, cudaEventDisableTiming);
        cfg = true;
    }

    // fork: convln (-> xs) on sA, mask pack on sB, both off the main stream
    cudaEventRecord(ef0, 0);
    cudaStreamWaitEvent(sA, ef0, 0);
    convln_kernel<<<NB * NKV, CDIM, 0, sA>>>(x, sr_w, sr_b, ln_g, ln_b, xsh, xsl);
    cudaEventRecord(eA, sA);

    cudaEventRecord(ef1, 0);
    cudaStreamWaitEvent(sB, ef1, 0);
    pack_mask_kernel<<<NB * NHEAD * NTOK * NKV / 256, 256, 0, sB>>>(mask, maskp);
    cudaEventRecord(eB, sB);

    // main: all fp32->bf16x2 splits in one launch
    split_all_kernel<<<(SPLIT_TOT + 255) / 256, 256>>>(
        x, q_w1, k_w1, v_w1, q_w2, k_w2, v_w2, proj_w,
        xh, xl, qw1h, qw1l, kvw1h, kvw1l, qw2h, qw2l, kw2h, kw2l, vw2h, vw2l, pwh, pwl);

    cudaStreamWaitEvent(0, eA, 0);   // xs ready for kv1

    // stage 1 group: q1 (128 CTAs) + kv1 (64 CTAs)
    {
        GemmGroup g = {};
        g.base1 = 128; g.base2 = 192;
        g.gx[0] = 1; g.Ah[0] = xh;  g.Al[0] = xl;  g.Bh[0] = qw1h;  g.Bl[0] = qw1l;
        g.Chi[0] = qlh;  g.Clo[0] = qll;  g.lda[0] = CDIM; g.N[0] = RLOW;    g.K[0] = CDIM;
        g.gx[1] = 2; g.Ah[1] = xsh; g.Al[1] = xsl; g.Bh[1] = kvw1h; g.Bl[1] = kvw1l;
        g.Chi[1] = kvlh; g.Clo[1] = kvll; g.lda[1] = CDIM; g.N[1] = 2 * RLOW; g.K[1] = CDIM;
        gemm3g_kernel<1><<<192, 256, SM1>>>(g);
    }

    // stage 2 group: q2 (256 CTAs) + k2 (64) + v2 (64, transposed out)
    {
        GemmGroup g = {};
        g.base1 = 256; g.base2 = 320;
        g.gx[0] = 4; g.Ah[0] = qlh; g.Al[0] = qll; g.Bh[0] = qw2h; g.Bl[0] = qw2l;
        g.Chi[0] = q2h; g.Clo[0] = q2l; g.lda[0] = RLOW; g.N[0] = CDIM; g.K[0] = RLOW;
        g.gx[1] = 4; g.Ah[1] = kvlh; g.Al[1] = kvll; g.Bh[1] = kw2h; g.Bl[1] = kw2l;
        g.Chi[1] = k2h; g.Clo[1] = k2l; g.lda[1] = 2 * RLOW; g.N[1] = CDIM; g.K[1] = RLOW;
        g.gx[2] = 4; g.Ah[2] = kvlh + RLOW; g.Al[2] = kvll + RLOW; g.Bh[2] = vw2h; g.Bl[2] = vw2l;
        g.Vth[2] = vth; g.Vtl[2] = vtl; g.lda[2] = 2 * RLOW; g.N[2] = CDIM; g.K[2] = RLOW;
        gemm3g_kernel<2><<<384, 256, SM2>>>(g);
    }

    cudaStreamWaitEvent(0, eB, 0);   // packed mask ready

    // attention (HMMA, 4 q-subtiles per CTA, Q double-buffered, bit mask)
    attn_kernel<<<dim3(2, NB * NHEAD), 256, ATTN_SMEM>>>(q2h, q2l, k2h, k2l,
        vth, vtl, maskp, aoh, aol);

    // output projection
    {
        GemmGroup g = {};
        g.base1 = 256; g.base2 = 256;
        g.gx[0] = 4; g.Ah[0] = aoh; g.Al[0] = aol; g.Bh[0] = pwh; g.Bl[0] = pwl;
        g.C[0] = out; g.bias[0] = proj_b; g.lda[0] = CDIM; g.N[0] = CDIM; g.K[0] = CDIM;
        gemm3g_kernel<2><<<256, 256, SM2>>>(g);
    }
}

// round 14
// speedup vs baseline: 1.0092x; 1.0092x over previous
#include <cuda_runtime.h>
#include <cuda_bf16.h>
#include <math.h>
#include <stdint.h>

// ---------------------------------------------------------------------------
// changeAttention on GB300 (plain sm_103 -> mma.sync HMMA).
// bf16x3 split grouped GEMMs + bf16x3 HMMA attention (bit-packed mask).
// Single stream (R13 fork/join regressed; reverted).
//   B=8, N=1024, C=512, heads=8, d=64, r=128, SR=2 -> Nn=256
// ---------------------------------------------------------------------------

#define NB    8
#define NTOK  1024
#define CDIM  512
#define NHEAD 8
#define HD    64
#define RLOW  128
#define NKV   256
#define MROW  (NB * NTOK)   // 8192
#define MKV   (NB * NKV)    // 2048

typedef __nv_bfloat16 bf16;

// ---------------- scratch (device globals) ----------------
__device__ __align__(128) bf16 g_xh  [MROW * CDIM],      g_xl  [MROW * CDIM];
__device__ __align__(128) bf16 g_qw1h[RLOW * CDIM],      g_qw1l[RLOW * CDIM];
__device__ __align__(128) bf16 g_kvw1h[2 * RLOW * CDIM], g_kvw1l[2 * RLOW * CDIM];
__device__ __align__(128) bf16 g_qw2h[CDIM * RLOW],      g_qw2l[CDIM * RLOW];
__device__ __align__(128) bf16 g_kw2h[CDIM * RLOW],      g_kw2l[CDIM * RLOW];
__device__ __align__(128) bf16 g_vw2h[CDIM * RLOW],      g_vw2l[CDIM * RLOW];
__device__ __align__(128) bf16 g_pwh [CDIM * CDIM],      g_pwl [CDIM * CDIM];
__device__ __align__(128) bf16 g_qlh [MROW * RLOW],      g_qll [MROW * RLOW];
__device__ __align__(128) bf16 g_xsh [MKV  * CDIM],      g_xsl [MKV  * CDIM];
__device__ __align__(128) bf16 g_kvlh[MKV * 2 * RLOW],   g_kvll[MKV * 2 * RLOW];
__device__ __align__(128) bf16 g_q2h [MROW * CDIM],      g_q2l [MROW * CDIM];
__device__ __align__(128) bf16 g_k2h [MKV  * CDIM],      g_k2l [MKV  * CDIM];
__device__ __align__(128) bf16 g_vth [MKV  * CDIM],      g_vtl [MKV  * CDIM];  // (b,c,m)
__device__ __align__(128) bf16 g_aoh [MROW * CDIM],      g_aol [MROW * CDIM];
__device__ __align__(128) uint32_t g_maskp[NB * NHEAD * NTOK * (NKV / 32)];    // 2 MB

// ---------------- PTX helpers ----------------
__device__ __forceinline__ uint32_t smem_u32(const void* p) {
    uint32_t a;
    asm("{ .reg .u64 t; cvta.to.shared.u64 t, %1; cvt.u32.u64 %0, t; }" : "=r"(a) : "l"(p));
    return a;
}
#define CP16(d, s)   asm volatile("cp.async.ca.shared.global [%0], [%1], 16;" :: "r"(d), "l"(s))
#define CP_COMMIT()  asm volatile("cp.async.commit_group;" ::: "memory")
#define CP_WAIT1()   asm volatile("cp.async.wait_group 1;" ::: "memory")
#define CP_WAIT0()   asm volatile("cp.async.wait_group 0;" ::: "memory")

#define LDMX4(r, addr)                                                         \
    asm volatile("ldmatrix.sync.aligned.m8n8.x4.shared.b16 {%0,%1,%2,%3}, [%4];" \
        : "=r"((r)[0]), "=r"((r)[1]), "=r"((r)[2]), "=r"((r)[3]) : "r"(addr))

#define MMA(d, a, b0, b1)                                                      \
    asm volatile("mma.sync.aligned.m16n8k16.row.col.f32.bf16.bf16.f32 "        \
        "{%0,%1,%2,%3},{%4,%5,%6,%7},{%8,%9},{%0,%1,%2,%3};"                   \
        : "+f"((d)[0]), "+f"((d)[1]), "+f"((d)[2]), "+f"((d)[3])               \
        : "r"((a)[0]), "r"((a)[1]), "r"((a)[2]), "r"((a)[3]), "r"(b0), "r"(b1))

__device__ __forceinline__ void pack_hl(float a, float b, uint32_t& h, uint32_t& l) {
    __nv_bfloat162 hh = __floats2bfloat162_rn(a, b);
    h = *reinterpret_cast<uint32_t*>(&hh);
    __nv_bfloat162 ll = __floats2bfloat162_rn(a - __bfloat162float(hh.x),
                                              b - __bfloat162float(hh.y));
    l = *reinterpret_cast<uint32_t*>(&ll);
}

// ---------------------------------------------------------------------------
// Grouped bf16x3 GEMM: up to 3 problems per launch, linear CTA decode.
// ---------------------------------------------------------------------------
#define TROWS 40

struct GemmGroup {
    int base1, base2;
    int gx[3];
    const bf16 *Ah[3], *Al[3], *Bh[3], *Bl[3];
    bf16 *Chi[3], *Clo[3], *Vth[3], *Vtl[3];
    float *C[3];
    const float *bias[3];
    int lda[3], N[3], K[3];
};

template<int NMI>
__device__ __forceinline__ void stage_loadT(
    const bf16* __restrict__ Ah, const bf16* __restrict__ Al, int lda,
    const bf16* __restrict__ Bh, const bf16* __restrict__ Bl,
    int m0, int n0, int K, int k0, uint32_t st, int tid)
{
    constexpr int ATB = 64 * NMI * TROWS * 2;
    constexpr int BTB = 128 * TROWS * 2;
    const bf16* a0 = Ah + (size_t)m0 * lda + k0;
    const bf16* a1 = Al + (size_t)m0 * lda + k0;
    const bf16* b0 = Bh + (size_t)n0 * K + k0;
    const bf16* b1 = Bl + (size_t)n0 * K + k0;
#pragma unroll
    for (int i = tid; i < 64 * NMI * 4; i += 256) {
        int r = i >> 2, c = i & 3;
        CP16(st + r * 80 + c * 16,       a0 + (size_t)r * lda + c * 8);
        CP16(st + ATB + r * 80 + c * 16, a1 + (size_t)r * lda + c * 8);
    }
#pragma unroll
    for (int i = tid; i < 512; i += 256) {
        int r = i >> 2, c = i & 3;
        CP16(st + 2 * ATB + r * 80 + c * 16,       b0 + (size_t)r * K + c * 8);
        CP16(st + 2 * ATB + BTB + r * 80 + c * 16, b1 + (size_t)r * K + c * 8);
    }
}

__device__ __forceinline__ uint32_t frag_addr(uint32_t tile, int row0, int kstep, int lane) {
    return tile + ((row0 + (lane & 15)) * TROWS + kstep * 16 + (lane >> 4) * 8) * 2;
}

template<int NMI>
__global__ void __launch_bounds__(256, 2) gemm3g_kernel(GemmGroup g)
{
    constexpr int ATB = 64 * NMI * TROWS * 2;
    constexpr int BTB = 128 * TROWS * 2;
    constexpr int STB = 2 * ATB + 2 * BTB;
    extern __shared__ char smem[];
    const uint32_t sb = smem_u32(smem);
    const int tid = threadIdx.x, lane = tid & 31, wid = tid >> 5;
    const int warp_m = wid >> 1, warp_n = wid & 1;

    const int cta = blockIdx.x;
    const int p = (cta >= g.base1) + (cta >= g.base2);
    const int local = cta - (p == 2 ? g.base2 : (p == 1 ? g.base1 : 0));
    const int gx = g.gx[p];
    const int m0 = (local / gx) * (64 * NMI), n0 = (local % gx) * 128;
    const bf16 *Ah = g.Ah[p], *Al = g.Al[p], *Bh = g.Bh[p], *Bl = g.Bl[p];
    const int lda = g.lda[p], N = g.N[p], K = g.K[p];
    const int nch = K >> 5;

    float acc[NMI][8][4];
#pragma unroll
    for (int i = 0; i < NMI; i++)
#pragma unroll
        for (int j = 0; j < 8; j++)
#pragma unroll
            for (int t = 0; t < 4; t++) acc[i][j][t] = 0.f;

    stage_loadT<NMI>(Ah, Al, lda, Bh, Bl, m0, n0, K, 0, sb, tid);
    CP_COMMIT();

    for (int ch = 0; ch < nch; ch++) {
        if (ch + 1 < nch) {
            stage_loadT<NMI>(Ah, Al, lda, Bh, Bl, m0, n0, K, (ch + 1) << 5,
                             sb + ((ch + 1) & 1) * STB, tid);
            CP_COMMIT();
            CP_WAIT1();
        } else {
            CP_WAIT0();
        }
        __syncthreads();

        const uint32_t st = sb + (ch & 1) * STB;
#pragma unroll
        for (int ks = 0; ks < 2; ks++) {
            uint32_t ah[NMI][4], al[NMI][4], bh[4][4], bl[4][4];
#pragma unroll
            for (int mi = 0; mi < NMI; mi++) {
                LDMX4(ah[mi], frag_addr(st,       warp_m * 16 * NMI + mi * 16, ks, lane));
                LDMX4(al[mi], frag_addr(st + ATB, warp_m * 16 * NMI + mi * 16, ks, lane));
            }
#pragma unroll
            for (int q = 0; q < 4; q++) {
                LDMX4(bh[q], frag_addr(st + 2 * ATB,       warp_n * 64 + q * 16, ks, lane));
                LDMX4(bl[q], frag_addr(st + 2 * ATB + BTB, warp_n * 64 + q * 16, ks, lane));
            }
#pragma unroll
            for (int mi = 0; mi < NMI; mi++)
#pragma unroll
                for (int q = 0; q < 4; q++) {
                    MMA(acc[mi][2 * q],     ah[mi], bh[q][0], bh[q][2]);
                    MMA(acc[mi][2 * q + 1], ah[mi], bh[q][1], bh[q][3]);
                    MMA(acc[mi][2 * q],     ah[mi], bl[q][0], bl[q][2]);
                    MMA(acc[mi][2 * q + 1], ah[mi], bl[q][1], bl[q][3]);
                    MMA(acc[mi][2 * q],     al[mi], bh[q][0], bh[q][2]);
                    MMA(acc[mi][2 * q + 1], al[mi], bh[q][1], bh[q][3]);
                }
        }
        __syncthreads();
    }

    float* C = g.C[p];
    bf16 *Chi = g.Chi[p], *Clo = g.Clo[p], *Vth = g.Vth[p], *Vtl = g.Vtl[p];
    const float* bias = g.bias[p];
    const int gr = lane >> 2, c2 = (lane & 3) * 2;
#pragma unroll
    for (int mi = 0; mi < NMI; mi++)
#pragma unroll
        for (int hh = 0; hh < 2; hh++) {
            const int row = m0 + warp_m * 16 * NMI + mi * 16 + hh * 8 + gr;
#pragma unroll
            for (int ni = 0; ni < 8; ni++) {
                const int col = n0 + warp_n * 64 + ni * 8 + c2;
                float v0 = acc[mi][ni][hh * 2 + 0];
                float v1 = acc[mi][ni][hh * 2 + 1];
                if (bias) { v0 += bias[col]; v1 += bias[col + 1]; }
                const size_t off = (size_t)row * N + col;
                if (C) *(float2*)(C + off) = make_float2(v0, v1);
                if (Chi || Vth) {
                    bf16 h0 = __float2bfloat16(v0), h1 = __float2bfloat16(v1);
                    bf16 l0 = __float2bfloat16(v0 - __bfloat162float(h0));
                    bf16 l1 = __float2bfloat16(v1 - __bfloat162float(h1));
                    if (Chi) {
                        *(__nv_bfloat162*)(Chi + off) = __nv_bfloat162(h0, h1);
                        *(__nv_bfloat162*)(Clo + off) = __nv_bfloat162(l0, l1);
                    }
                    if (Vth) {  // transposed (b, c, m) layout
                        size_t toff = ((size_t)((row >> 8) * CDIM + col)) * NKV + (row & 255);
                        Vth[toff] = h0; Vth[toff + NKV] = h1;
                        Vtl[toff] = l0; Vtl[toff + NKV] = l1;
                    }
                }
            }
        }
}

// ---------------- fp32 -> (bf16 hi, bf16 lo) splits (one launch) ----------------
__device__ __forceinline__ void split4(const float* __restrict__ s, bf16* __restrict__ h,
                                       bf16* __restrict__ l, int i) {
    float4 v = ((const float4*)s)[i];
    bf16 h0 = __float2bfloat16(v.x), h1 = __float2bfloat16(v.y);
    bf16 h2 = __float2bfloat16(v.z), h3 = __float2bfloat16(v.w);
    ((__nv_bfloat162*)h)[i * 2 + 0] = __nv_bfloat162(h0, h1);
    ((__nv_bfloat162*)h)[i * 2 + 1] = __nv_bfloat162(h2, h3);
    ((__nv_bfloat162*)l)[i * 2 + 0] = __nv_bfloat162(
        __float2bfloat16(v.x - __bfloat162float(h0)),
        __float2bfloat16(v.y - __bfloat162float(h1)));
    ((__nv_bfloat162*)l)[i * 2 + 1] = __nv_bfloat162(
        __float2bfloat16(v.z - __bfloat162float(h2)),
        __float2bfloat16(v.w - __bfloat162float(h3)));
}

#define XN4 (MROW * CDIM / 4)        // 1048576
#define WN4 16384                    // RLOW*CDIM/4
#define PN4 (CDIM * CDIM / 4)        // 65536
#define SPLIT_TOT (XN4 + 6 * WN4 + PN4)

__global__ void split_all_kernel(
    const float* __restrict__ x,
    const float* __restrict__ qw1, const float* __restrict__ kw1,
    const float* __restrict__ vw1, const float* __restrict__ qw2,
    const float* __restrict__ kw2, const float* __restrict__ vw2,
    const float* __restrict__ pw,
    bf16* __restrict__ xh, bf16* __restrict__ xl,
    bf16* __restrict__ qw1h, bf16* __restrict__ qw1l,
    bf16* __restrict__ kvw1h, bf16* __restrict__ kvw1l,
    bf16* __restrict__ qw2h, bf16* __restrict__ qw2l,
    bf16* __restrict__ kw2h, bf16* __restrict__ kw2l,
    bf16* __restrict__ vw2h, bf16* __restrict__ vw2l,
    bf16* __restrict__ pwh, bf16* __restrict__ pwl)
{
    int i = blockIdx.x * blockDim.x + threadIdx.x;
    if (i < XN4) { split4(x, xh, xl, i); return; }
    i -= XN4;
    if (i < 6 * WN4) {
        int j = i / WN4, off = i - j * WN4;
        switch (j) {
            case 0: split4(qw1, qw1h, qw1l, off); break;
            case 1: split4(kw1, kvw1h, kvw1l, off); break;
            case 2: split4(vw1, kvw1h + 4 * WN4, kvw1l + 4 * WN4, off); break;
            case 3: split4(qw2, qw2h, qw2l, off); break;
            case 4: split4(kw2, kw2h, kw2l, off); break;
            default: split4(vw2, vw2h, vw2l, off); break;
        }
    } else {
        int off = i - 6 * WN4;
        if (off < PN4) split4(pw, pwh, pwl, off);
    }
}

// ---------------- mask int32 -> bit-packed (ballot, coalesced) ----------------
__global__ void pack_mask_kernel(const int* __restrict__ m, uint32_t* __restrict__ o) {
    int idx = blockIdx.x * blockDim.x + threadIdx.x;
    uint32_t b = __ballot_sync(0xffffffffu, m[idx] != 0);
    if ((threadIdx.x & 31) == 0) o[idx >> 5] = b;
}

// ---------------------------------------------------------------------------
// Depthwise 2x2/s2 conv + bias + LayerNorm(C); writes bf16 (hi,lo) split.
// ---------------------------------------------------------------------------
__global__ void convln_kernel(const float* __restrict__ x, const float* __restrict__ sr_w,
                              const float* __restrict__ sr_b, const float* __restrict__ ln_g,
                              const float* __restrict__ ln_b,
                              bf16* __restrict__ xsh, bf16* __restrict__ xsl) {
    const int b = blockIdx.x >> 8, n = blockIdx.x & 255;
    const int ph = n >> 4, pw = n & 15, c = threadIdx.x;
    const float* xb = x + (size_t)b * NTOK * CDIM;
    const int r0 = ph * 64 + pw * 2;

    float val = xb[(size_t)(r0)      * CDIM + c] * sr_w[c * 4 + 0]
              + xb[(size_t)(r0 + 1)  * CDIM + c] * sr_w[c * 4 + 1]
              + xb[(size_t)(r0 + 32) * CDIM + c] * sr_w[c * 4 + 2]
              + xb[(size_t)(r0 + 33) * CDIM + c] * sr_w[c * 4 + 3]
              + sr_b[c];

    float s1 = val, s2 = val * val;
#pragma unroll
    for (int o = 16; o > 0; o >>= 1) {
        s1 += __shfl_xor_sync(0xffffffffu, s1, o);
        s2 += __shfl_xor_sync(0xffffffffu, s2, o);
    }
    __shared__ float r1[16], r2[16];
    const int w = c >> 5, lane = c & 31;
    if (lane == 0) { r1[w] = s1; r2[w] = s2; }
    __syncthreads();
    float t1 = 0.f, t2 = 0.f;
#pragma unroll
    for (int i = 0; i < 16; i++) { t1 += r1[i]; t2 += r2[i]; }
    const float mu  = t1 * (1.f / 512.f);
    const float var = t2 * (1.f / 512.f) - mu * mu;
    const float inv = rsqrtf(var + 1e-5f);
    const float o = (val - mu) * inv * ln_g[c] + ln_b[c];
    const size_t off = (size_t)(b * NKV + n) * CDIM + c;
    bf16 h = __float2bfloat16(o);
    xsh[off] = h;
    xsl[off] = __float2bfloat16(o - __bfloat162float(h));
}

// ---------------------------------------------------------------------------
// HMMA attention: CTA = (b, h, 512 q rows as 4 subtiles of 128). 8 warps.
// K/V staged once; Q double-buffered; mask read as packed bits (8 words/row).
// ---------------------------------------------------------------------------
#define AQS 72
#define AKS 72
#define AVS 264
#define QBUF(i) ((i) * 36864)
#define KH_OFF 73728
#define KL_OFF 110592
#define VH_OFF 147456
#define VL_OFF 181248
#define ATTN_SMEM 215040

__global__ void __launch_bounds__(256, 1) attn_kernel(
    const bf16* __restrict__ qh, const bf16* __restrict__ ql,
    const bf16* __restrict__ kh, const bf16* __restrict__ kl,
    const bf16* __restrict__ vth, const bf16* __restrict__ vtl,
    const uint32_t* __restrict__ maskp,
    bf16* __restrict__ aoh, bf16* __restrict__ aol)
{
    extern __shared__ char smem[];
    const uint32_t sb = smem_u32(smem);
    const int qt = blockIdx.x;          // 0..1 (512 q rows each)
    const int bh = blockIdx.y;          // 0..63
    const int b = bh >> 3, h = bh & 7;
    const int tid = threadIdx.x, lane = tid & 31, wid = tid >> 5;

    const bf16* khg = kh + ((size_t)(b * NKV)) * CDIM + h * HD;
    const bf16* klg = kl + ((size_t)(b * NKV)) * CDIM + h * HD;
    const bf16* vhg = vth + ((size_t)(b * CDIM + h * HD)) * NKV;
    const bf16* vlg = vtl + ((size_t)(b * CDIM + h * HD)) * NKV;
    const bf16* qhg0 = qh + ((size_t)(b * NTOK + qt * 512)) * CDIM + h * HD;
    const bf16* qlg0 = ql + ((size_t)(b * NTOK + qt * 512)) * CDIM + h * HD;

    // stage K (256x64), Vt (64x256), Q subtile 0
#pragma unroll
    for (int i = tid; i < 2048; i += 256) {
        int r = i >> 3, c = i & 7;
        CP16(sb + KH_OFF + r * (AKS * 2) + c * 16, khg + (size_t)r * CDIM + c * 8);
        CP16(sb + KL_OFF + r * (AKS * 2) + c * 16, klg + (size_t)r * CDIM + c * 8);
    }
#pragma unroll
    for (int i = tid; i < 2048; i += 256) {
        int r = i >> 5, c = i & 31;
        CP16(sb + VH_OFF + r * (AVS * 2) + c * 16, vhg + (size_t)r * NKV + c * 8);
        CP16(sb + VL_OFF + r * (AVS * 2) + c * 16, vlg + (size_t)r * NKV + c * 8);
    }
#pragma unroll
    for (int i = tid; i < 1024; i += 256) {
        int r = i >> 3, c = i & 7;
        CP16(sb + QBUF(0) + r * (AQS * 2) + c * 16,         qhg0 + (size_t)r * CDIM + c * 8);
        CP16(sb + QBUF(0) + 18432 + r * (AQS * 2) + c * 16, qlg0 + (size_t)r * CDIM + c * 8);
    }
    CP_COMMIT();

    const int row0 = wid * 16;
    const int gr = lane >> 2, cq = (lane & 3) * 2;
    const float scale = 0.125f;

    for (int s = 0; s < 4; s++) {
        CP_WAIT0();
        __syncthreads();
        const uint32_t qb = sb + QBUF(s & 1);
        const int qrow0 = qt * 512 + s * 128;

        float acc[32][4];
#pragma unroll
        for (int na = 0; na < 32; na++)
#pragma unroll
            for (int t = 0; t < 4; t++) acc[na][t] = 0.f;

#pragma unroll
        for (int ks = 0; ks < 4; ks++) {
            uint32_t a_h[4], a_l[4];
            LDMX4(a_h, qb + ((row0 + (lane & 15)) * AQS + ks * 16 + (lane >> 4) * 8) * 2);
            LDMX4(a_l, qb + 18432 + ((row0 + (lane & 15)) * AQS + ks * 16 + (lane >> 4) * 8) * 2);
#pragma unroll
            for (int nb = 0; nb < 16; nb++) {
                uint32_t k_h[4], k_l[4];
                LDMX4(k_h, sb + KH_OFF + ((nb * 16 + (lane & 15)) * AKS + ks * 16 + (lane >> 4) * 8) * 2);
                LDMX4(k_l, sb + KL_OFF + ((nb * 16 + (lane & 15)) * AKS + ks * 16 + (lane >> 4) * 8) * 2);
                MMA(acc[2 * nb],     a_h, k_h[0], k_h[2]);
                MMA(acc[2 * nb + 1], a_h, k_h[1], k_h[3]);
                MMA(acc[2 * nb],     a_h, k_l[0], k_l[2]);
                MMA(acc[2 * nb + 1], a_h, k_l[1], k_l[3]);
                MMA(acc[2 * nb],     a_l, k_h[0], k_h[2]);
                MMA(acc[2 * nb + 1], a_l, k_h[1], k_h[3]);
            }
        }

        // prefetch next Q subtile into other buffer (overlaps softmax + PV)
        if (s < 3) {
            const bf16* nqh = qhg0 + (size_t)(s + 1) * 128 * CDIM;
            const bf16* nql = qlg0 + (size_t)(s + 1) * 128 * CDIM;
            const uint32_t nqb = sb + QBUF((s + 1) & 1);
#pragma unroll
            for (int i = tid; i < 1024; i += 256) {
                int r = i >> 3, c = i & 7;
                CP16(nqb + r * (AQS * 2) + c * 16,         nqh + (size_t)r * CDIM + c * 8);
                CP16(nqb + 18432 + r * (AQS * 2) + c * 16, nql + (size_t)r * CDIM + c * 8);
            }
            CP_COMMIT();
        }

        // packed mask: 8 words per row; col c -> word c>>5, bit c&31
        const uint32_t* mp0 = maskp + ((size_t)bh * NTOK + qrow0 + row0 + gr) * 8;
        uint32_t w0[8], w1[8];
        *(uint4*)(w0)     = *(const uint4*)(mp0);
        *(uint4*)(w0 + 4) = *(const uint4*)(mp0 + 4);
        *(uint4*)(w1)     = *(const uint4*)(mp0 + 64);
        *(uint4*)(w1 + 4) = *(const uint4*)(mp0 + 68);

        float mx0 = -1e30f, mx1 = -1e30f;
#pragma unroll
        for (int na = 0; na < 32; na++) {
            const int wrd = na >> 2, bb = ((na & 3) << 3) | cq;
            float s0 = acc[na][0] * scale; if ((w0[wrd] >> bb) & 1)       s0 = -1e30f;
            float s1 = acc[na][1] * scale; if ((w0[wrd] >> (bb + 1)) & 1) s1 = -1e30f;
            float s2 = acc[na][2] * scale; if ((w1[wrd] >> bb) & 1)       s2 = -1e30f;
            float s3 = acc[na][3] * scale; if ((w1[wrd] >> (bb + 1)) & 1) s3 = -1e30f;
            acc[na][0] = s0; acc[na][1] = s1; acc[na][2] = s2; acc[na][3] = s3;
            mx0 = fmaxf(mx0, fmaxf(s0, s1));
            mx1 = fmaxf(mx1, fmaxf(s2, s3));
        }
        mx0 = fmaxf(mx0, __shfl_xor_sync(0xffffffffu, mx0, 1));
        mx0 = fmaxf(mx0, __shfl_xor_sync(0xffffffffu, mx0, 2));
        mx1 = fmaxf(mx1, __shfl_xor_sync(0xffffffffu, mx1, 1));
        mx1 = fmaxf(mx1, __shfl_xor_sync(0xffffffffu, mx1, 2));

        float sum0 = 0.f, sum1 = 0.f;
#pragma unroll
        for (int na = 0; na < 32; na++) {
            float e0 = __expf(acc[na][0] - mx0);
            float e1 = __expf(acc[na][1] - mx0);
            float e2 = __expf(acc[na][2] - mx1);
            float e3 = __expf(acc[na][3] - mx1);
            acc[na][0] = e0; acc[na][1] = e1; acc[na][2] = e2; acc[na][3] = e3;
            sum0 += e0 + e1; sum1 += e2 + e3;
        }
        sum0 += __shfl_xor_sync(0xffffffffu, sum0, 1);
        sum0 += __shfl_xor_sync(0xffffffffu, sum0, 2);
        sum1 += __shfl_xor_sync(0xffffffffu, sum1, 1);
        sum1 += __shfl_xor_sync(0xffffffffu, sum1, 2);

        float acco[8][4];
#pragma unroll
        for (int na = 0; na < 8; na++)
#pragma unroll
            for (int t = 0; t < 4; t++) acco[na][t] = 0.f;

#pragma unroll
        for (int t = 0; t < 16; t++) {
            uint32_t p_h[4], p_l[4];
            pack_hl(acc[2 * t][0],     acc[2 * t][1],     p_h[0], p_l[0]);
            pack_hl(acc[2 * t][2],     acc[2 * t][3],     p_h[1], p_l[1]);
            pack_hl(acc[2 * t + 1][0], acc[2 * t + 1][1], p_h[2], p_l[2]);
            pack_hl(acc[2 * t + 1][2], acc[2 * t + 1][3], p_h[3], p_l[3]);
#pragma unroll
            for (int vb = 0; vb < 4; vb++) {
                uint32_t v_h[4], v_l[4];
                LDMX4(v_h, sb + VH_OFF + ((vb * 16 + (lane & 15)) * AVS + t * 16 + (lane >> 4) * 8) * 2);
                LDMX4(v_l, sb + VL_OFF + ((vb * 16 + (lane & 15)) * AVS + t * 16 + (lane >> 4) * 8) * 2);
                MMA(acco[2 * vb],     p_h, v_h[0], v_h[2]);
                MMA(acco[2 * vb + 1], p_h, v_h[1], v_h[3]);
                MMA(acco[2 * vb],     p_h, v_l[0], v_l[2]);
                MMA(acco[2 * vb + 1], p_h, v_l[1], v_l[3]);
                MMA(acco[2 * vb],     p_l, v_h[0], v_h[2]);
                MMA(acco[2 * vb + 1], p_l, v_h[1], v_h[3]);
            }
        }

        const float i0 = 1.f / sum0, i1 = 1.f / sum1;
        const size_t rbase = ((size_t)(b * NTOK + qrow0 + row0 + gr)) * CDIM + h * HD;
#pragma unroll
        for (int na = 0; na < 8; na++) {
            const int c = na * 8 + cq;
            uint32_t h0, l0, h1, l1;
            pack_hl(acco[na][0] * i0, acco[na][1] * i0, h0, l0);
            pack_hl(acco[na][2] * i1, acco[na][3] * i1, h1, l1);
            *(uint32_t*)(aoh + rbase + c)            = h0;
            *(uint32_t*)(aol + rbase + c)            = l0;
            *(uint32_t*)(aoh + rbase + 8 * CDIM + c) = h1;
            *(uint32_t*)(aol + rbase + 8 * CDIM + c) = l1;
        }
    }
}

// ---------------------------------------------------------------------------
extern "C" void kernel_launch(void* const* d_in, const int* in_sizes, int n_in,
                              void* d_out, int out_size) {
    const float* x      = (const float*)d_in[0];
    const int*   mask   = (const int*)d_in[1];
    const float* q_w1   = (const float*)d_in[2];
    const float* q_w2   = (const float*)d_in[3];
    const float* k_w1   = (const float*)d_in[4];
    const float* k_w2   = (const float*)d_in[5];
    const float* v_w1   = (const float*)d_in[6];
    const float* v_w2   = (const float*)d_in[7];
    const float* sr_w   = (const float*)d_in[8];
    const float* sr_b   = (const float*)d_in[9];
    const float* ln_g   = (const float*)d_in[10];
    const float* ln_b   = (const float*)d_in[11];
    const float* proj_w = (const float*)d_in[12];
    const float* proj_b = (const float*)d_in[13];
    float* out = (float*)d_out;

    bf16 *xh, *xl, *qw1h, *qw1l, *kvw1h, *kvw1l;
    bf16 *qw2h, *qw2l, *kw2h, *kw2l, *vw2h, *vw2l, *pwh, *pwl;
    bf16 *qlh, *qll, *xsh, *xsl, *kvlh, *kvll;
    bf16 *q2h, *q2l, *k2h, *k2l, *vth, *vtl, *aoh, *aol;
    uint32_t* maskp;
    cudaGetSymbolAddress((void**)&xh, g_xh);       cudaGetSymbolAddress((void**)&xl, g_xl);
    cudaGetSymbolAddress((void**)&qw1h, g_qw1h);   cudaGetSymbolAddress((void**)&qw1l, g_qw1l);
    cudaGetSymbolAddress((void**)&kvw1h, g_kvw1h); cudaGetSymbolAddress((void**)&kvw1l, g_kvw1l);
    cudaGetSymbolAddress((void**)&qw2h, g_qw2h);   cudaGetSymbolAddress((void**)&qw2l, g_qw2l);
    cudaGetSymbolAddress((void**)&kw2h, g_kw2h);   cudaGetSymbolAddress((void**)&kw2l, g_kw2l);
    cudaGetSymbolAddress((void**)&vw2h, g_vw2h);   cudaGetSymbolAddress((void**)&vw2l, g_vw2l);
    cudaGetSymbolAddress((void**)&pwh, g_pwh);     cudaGetSymbolAddress((void**)&pwl, g_pwl);
    cudaGetSymbolAddress((void**)&qlh, g_qlh);     cudaGetSymbolAddress((void**)&qll, g_qll);
    cudaGetSymbolAddress((void**)&xsh, g_xsh);     cudaGetSymbolAddress((void**)&xsl, g_xsl);
    cudaGetSymbolAddress((void**)&kvlh, g_kvlh);   cudaGetSymbolAddress((void**)&kvll, g_kvll);
    cudaGetSymbolAddress((void**)&q2h, g_q2h);     cudaGetSymbolAddress((void**)&q2l, g_q2l);
    cudaGetSymbolAddress((void**)&k2h, g_k2h);     cudaGetSymbolAddress((void**)&k2l, g_k2l);
    cudaGetSymbolAddress((void**)&vth, g_vth);     cudaGetSymbolAddress((void**)&vtl, g_vtl);
    cudaGetSymbolAddress((void**)&aoh, g_aoh);     cudaGetSymbolAddress((void**)&aol, g_aol);
    cudaGetSymbolAddress((void**)&maskp, g_maskp);

    constexpr int SM1 = 2 * (2 * (64 * TROWS * 2) + 2 * (128 * TROWS * 2));   // 61440
    constexpr int SM2 = 2 * (2 * (128 * TROWS * 2) + 2 * (128 * TROWS * 2));  // 81920

    static bool cfg = false;
    if (!cfg) {
        cudaFuncSetAttribute(gemm3g_kernel<1>, cudaFuncAttributeMaxDynamicSharedMemorySize, SM1);
        cudaFuncSetAttribute(gemm3g_kernel<2>, cudaFuncAttributeMaxDynamicSharedMemorySize, SM2);
        cudaFuncSetAttribute(attn_kernel, cudaFuncAttributeMaxDynamicSharedMemorySize, ATTN_SMEM);
        cfg = true;
    }

    // mask pack first (packed result stays L2-resident for attention)
    pack_mask_kernel<<<NB * NHEAD * NTOK * NKV / 256, 256>>>(mask, maskp);

    // all fp32->bf16x2 splits in one launch
    split_all_kernel<<<(SPLIT_TOT + 255) / 256, 256>>>(
        x, q_w1, k_w1, v_w1, q_w2, k_w2, v_w2, proj_w,
        xh, xl, qw1h, qw1l, kvw1h, kvw1l, qw2h, qw2l, kw2h, kw2l, vw2h, vw2l, pwh, pwl);

    // spatial reduction + layernorm -> xs (hi,lo)
    convln_kernel<<<NB * NKV, CDIM>>>(x, sr_w, sr_b, ln_g, ln_b, xsh, xsl);

    // stage 1 group: q1 (128 CTAs) + kv1 (64 CTAs)
    {
        GemmGroup g = {};
        g.base1 = 128; g.base2 = 192;
        g.gx[0] = 1; g.Ah[0] = xh;  g.Al[0] = xl;  g.Bh[0] = qw1h;  g.Bl[0] = qw1l;
        g.Chi[0] = qlh;  g.Clo[0] = qll;  g.lda[0] = CDIM; g.N[0] = RLOW;    g.K[0] = CDIM;
        g.gx[1] = 2; g.Ah[1] = xsh; g.Al[1] = xsl; g.Bh[1] = kvw1h; g.Bl[1] = kvw1l;
        g.Chi[1] = kvlh; g.Clo[1] = kvll; g.lda[1] = CDIM; g.N[1] = 2 * RLOW; g.K[1] = CDIM;
        gemm3g_kernel<1><<<192, 256, SM1>>>(g);
    }

    // stage 2 group: q2 (256 CTAs) + k2 (64) + v2 (64, transposed out)
    {
        GemmGroup g = {};
        g.base1 = 256; g.base2 = 320;
        g.gx[0] = 4; g.Ah[0] = qlh; g.Al[0] = qll; g.Bh[0] = qw2h; g.Bl[0] = qw2l;
        g.Chi[0] = q2h; g.Clo[0] = q2l; g.lda[0] = RLOW; g.N[0] = CDIM; g.K[0] = RLOW;
        g.gx[1] = 4; g.Ah[1] = kvlh; g.Al[1] = kvll; g.Bh[1] = kw2h; g.Bl[1] = kw2l;
        g.Chi[1] = k2h; g.Clo[1] = k2l; g.lda[1] = 2 * RLOW; g.N[1] = CDIM; g.K[1] = RLOW;
        g.gx[2] = 4; g.Ah[2] = kvlh + RLOW; g.Al[2] = kvll + RLOW; g.Bh[2] = vw2h; g.Bl[2] = vw2l;
        g.Vth[2] = vth; g.Vtl[2] = vtl; g.lda[2] = 2 * RLOW; g.N[2] = CDIM; g.K[2] = RLOW;
        gemm3g_kernel<2><<<384, 256, SM2>>>(g);
    }

    // attention (HMMA, 4 q-subtiles per CTA, Q double-buffered, bit mask)
    attn_kernel<<<dim3(2, NB * NHEAD), 256, ATTN_SMEM>>>(q2h, q2l, k2h, k2l,
        vth, vtl, maskp, aoh, aol);

    // output projection
    {
        GemmGroup g = {};
        g.base1 = 256; g.base2 = 256;
        g.gx[0] = 4; g.Ah[0] = aoh; g.Al[0] = aol; g.Bh[0] = pwh; g.Bl[0] = pwl;
        g.C[0] = out; g.bias[0] = proj_b; g.lda[0] = CDIM; g.N[0] = CDIM; g.K[0] = CDIM;
        gemm3g_kernel<2><<<256, 256, SM2>>>(g);
    }
}

// round 15
// speedup vs baseline: 1.1738x; 1.1631x over previous
#include <cuda_runtime.h>
#include <cuda_bf16.h>
#include <math.h>
#include <stdint.h>

// ---------------------------------------------------------------------------
// changeAttention on GB300 (plain sm_103 -> mma.sync HMMA).
// bf16x3 split grouped GEMMs + bf16x3 HMMA attention (inline int32 mask —
// packed-mask experiment R13/R14 regressed: attention mask reads are hidden).
// convln fused into the split prep kernel.
//   B=8, N=1024, C=512, heads=8, d=64, r=128, SR=2 -> Nn=256
// ---------------------------------------------------------------------------

#define NB    8
#define NTOK  1024
#define CDIM  512
#define NHEAD 8
#define HD    64
#define RLOW  128
#define NKV   256
#define MROW  (NB * NTOK)   // 8192
#define MKV   (NB * NKV)    // 2048

typedef __nv_bfloat16 bf16;

// ---------------- scratch (device globals) ----------------
__device__ __align__(128) bf16 g_xh  [MROW * CDIM],      g_xl  [MROW * CDIM];
__device__ __align__(128) bf16 g_qw1h[RLOW * CDIM],      g_qw1l[RLOW * CDIM];
__device__ __align__(128) bf16 g_kvw1h[2 * RLOW * CDIM], g_kvw1l[2 * RLOW * CDIM];
__device__ __align__(128) bf16 g_qw2h[CDIM * RLOW],      g_qw2l[CDIM * RLOW];
__device__ __align__(128) bf16 g_kw2h[CDIM * RLOW],      g_kw2l[CDIM * RLOW];
__device__ __align__(128) bf16 g_vw2h[CDIM * RLOW],      g_vw2l[CDIM * RLOW];
__device__ __align__(128) bf16 g_pwh [CDIM * CDIM],      g_pwl [CDIM * CDIM];
__device__ __align__(128) bf16 g_qlh [MROW * RLOW],      g_qll [MROW * RLOW];
__device__ __align__(128) bf16 g_xsh [MKV  * CDIM],      g_xsl [MKV  * CDIM];
__device__ __align__(128) bf16 g_kvlh[MKV * 2 * RLOW],   g_kvll[MKV * 2 * RLOW];
__device__ __align__(128) bf16 g_q2h [MROW * CDIM],      g_q2l [MROW * CDIM];
__device__ __align__(128) bf16 g_k2h [MKV  * CDIM],      g_k2l [MKV  * CDIM];
__device__ __align__(128) bf16 g_vth [MKV  * CDIM],      g_vtl [MKV  * CDIM];  // (b,c,m)
__device__ __align__(128) bf16 g_aoh [MROW * CDIM],      g_aol [MROW * CDIM];

// ---------------- PTX helpers ----------------
__device__ __forceinline__ uint32_t smem_u32(const void* p) {
    uint32_t a;
    asm("{ .reg .u64 t; cvta.to.shared.u64 t, %1; cvt.u32.u64 %0, t; }" : "=r"(a) : "l"(p));
    return a;
}
#define CP16(d, s)   asm volatile("cp.async.ca.shared.global [%0], [%1], 16;" :: "r"(d), "l"(s))
#define CP_COMMIT()  asm volatile("cp.async.commit_group;" ::: "memory")
#define CP_WAIT1()   asm volatile("cp.async.wait_group 1;" ::: "memory")
#define CP_WAIT0()   asm volatile("cp.async.wait_group 0;" ::: "memory")

#define LDMX4(r, addr)                                                         \
    asm volatile("ldmatrix.sync.aligned.m8n8.x4.shared.b16 {%0,%1,%2,%3}, [%4];" \
        : "=r"((r)[0]), "=r"((r)[1]), "=r"((r)[2]), "=r"((r)[3]) : "r"(addr))

#define MMA(d, a, b0, b1)                                                      \
    asm volatile("mma.sync.aligned.m16n8k16.row.col.f32.bf16.bf16.f32 "        \
        "{%0,%1,%2,%3},{%4,%5,%6,%7},{%8,%9},{%0,%1,%2,%3};"                   \
        : "+f"((d)[0]), "+f"((d)[1]), "+f"((d)[2]), "+f"((d)[3])               \
        : "r"((a)[0]), "r"((a)[1]), "r"((a)[2]), "r"((a)[3]), "r"(b0), "r"(b1))

__device__ __forceinline__ void pack_hl(float a, float b, uint32_t& h, uint32_t& l) {
    __nv_bfloat162 hh = __floats2bfloat162_rn(a, b);
    h = *reinterpret_cast<uint32_t*>(&hh);
    __nv_bfloat162 ll = __floats2bfloat162_rn(a - __bfloat162float(hh.x),
                                              b - __bfloat162float(hh.y));
    l = *reinterpret_cast<uint32_t*>(&ll);
}

// ---------------------------------------------------------------------------
// Grouped bf16x3 GEMM: up to 3 problems per launch, linear CTA decode.
// ---------------------------------------------------------------------------
#define TROWS 40

struct GemmGroup {
    int base1, base2;
    int gx[3];
    const bf16 *Ah[3], *Al[3], *Bh[3], *Bl[3];
    bf16 *Chi[3], *Clo[3], *Vth[3], *Vtl[3];
    float *C[3];
    const float *bias[3];
    int lda[3], N[3], K[3];
};

template<int NMI>
__device__ __forceinline__ void stage_loadT(
    const bf16* __restrict__ Ah, const bf16* __restrict__ Al, int lda,
    const bf16* __restrict__ Bh, const bf16* __restrict__ Bl,
    int m0, int n0, int K, int k0, uint32_t st, int tid)
{
    constexpr int ATB = 64 * NMI * TROWS * 2;
    constexpr int BTB = 128 * TROWS * 2;
    const bf16* a0 = Ah + (size_t)m0 * lda + k0;
    const bf16* a1 = Al + (size_t)m0 * lda + k0;
    const bf16* b0 = Bh + (size_t)n0 * K + k0;
    const bf16* b1 = Bl + (size_t)n0 * K + k0;
#pragma unroll
    for (int i = tid; i < 64 * NMI * 4; i += 256) {
        int r = i >> 2, c = i & 3;
        CP16(st + r * 80 + c * 16,       a0 + (size_t)r * lda + c * 8);
        CP16(st + ATB + r * 80 + c * 16, a1 + (size_t)r * lda + c * 8);
    }
#pragma unroll
    for (int i = tid; i < 512; i += 256) {
        int r = i >> 2, c = i & 3;
        CP16(st + 2 * ATB + r * 80 + c * 16,       b0 + (size_t)r * K + c * 8);
        CP16(st + 2 * ATB + BTB + r * 80 + c * 16, b1 + (size_t)r * K + c * 8);
    }
}

__device__ __forceinline__ uint32_t frag_addr(uint32_t tile, int row0, int kstep, int lane) {
    return tile + ((row0 + (lane & 15)) * TROWS + kstep * 16 + (lane >> 4) * 8) * 2;
}

template<int NMI>
__global__ void __launch_bounds__(256, 2) gemm3g_kernel(GemmGroup g)
{
    constexpr int ATB = 64 * NMI * TROWS * 2;
    constexpr int BTB = 128 * TROWS * 2;
    constexpr int STB = 2 * ATB + 2 * BTB;
    extern __shared__ char smem[];
    const uint32_t sb = smem_u32(smem);
    const int tid = threadIdx.x, lane = tid & 31, wid = tid >> 5;
    const int warp_m = wid >> 1, warp_n = wid & 1;

    const int cta = blockIdx.x;
    const int p = (cta >= g.base1) + (cta >= g.base2);
    const int local = cta - (p == 2 ? g.base2 : (p == 1 ? g.base1 : 0));
    const int gx = g.gx[p];
    const int m0 = (local / gx) * (64 * NMI), n0 = (local % gx) * 128;
    const bf16 *Ah = g.Ah[p], *Al = g.Al[p], *Bh = g.Bh[p], *Bl = g.Bl[p];
    const int lda = g.lda[p], N = g.N[p], K = g.K[p];
    const int nch = K >> 5;

    float acc[NMI][8][4];
#pragma unroll
    for (int i = 0; i < NMI; i++)
#pragma unroll
        for (int j = 0; j < 8; j++)
#pragma unroll
            for (int t = 0; t < 4; t++) acc[i][j][t] = 0.f;

    stage_loadT<NMI>(Ah, Al, lda, Bh, Bl, m0, n0, K, 0, sb, tid);
    CP_COMMIT();

    for (int ch = 0; ch < nch; ch++) {
        if (ch + 1 < nch) {
            stage_loadT<NMI>(Ah, Al, lda, Bh, Bl, m0, n0, K, (ch + 1) << 5,
                             sb + ((ch + 1) & 1) * STB, tid);
            CP_COMMIT();
            CP_WAIT1();
        } else {
            CP_WAIT0();
        }
        __syncthreads();

        const uint32_t st = sb + (ch & 1) * STB;
#pragma unroll
        for (int ks = 0; ks < 2; ks++) {
            uint32_t ah[NMI][4], al[NMI][4], bh[4][4], bl[4][4];
#pragma unroll
            for (int mi = 0; mi < NMI; mi++) {
                LDMX4(ah[mi], frag_addr(st,       warp_m * 16 * NMI + mi * 16, ks, lane));
                LDMX4(al[mi], frag_addr(st + ATB, warp_m * 16 * NMI + mi * 16, ks, lane));
            }
#pragma unroll
            for (int q = 0; q < 4; q++) {
                LDMX4(bh[q], frag_addr(st + 2 * ATB,       warp_n * 64 + q * 16, ks, lane));
                LDMX4(bl[q], frag_addr(st + 2 * ATB + BTB, warp_n * 64 + q * 16, ks, lane));
            }
#pragma unroll
            for (int mi = 0; mi < NMI; mi++)
#pragma unroll
                for (int q = 0; q < 4; q++) {
                    MMA(acc[mi][2 * q],     ah[mi], bh[q][0], bh[q][2]);
                    MMA(acc[mi][2 * q + 1], ah[mi], bh[q][1], bh[q][3]);
                    MMA(acc[mi][2 * q],     ah[mi], bl[q][0], bl[q][2]);
                    MMA(acc[mi][2 * q + 1], ah[mi], bl[q][1], bl[q][3]);
                    MMA(acc[mi][2 * q],     al[mi], bh[q][0], bh[q][2]);
                    MMA(acc[mi][2 * q + 1], al[mi], bh[q][1], bh[q][3]);
                }
        }
        __syncthreads();
    }

    float* C = g.C[p];
    bf16 *Chi = g.Chi[p], *Clo = g.Clo[p], *Vth = g.Vth[p], *Vtl = g.Vtl[p];
    const float* bias = g.bias[p];
    const int gr = lane >> 2, c2 = (lane & 3) * 2;
#pragma unroll
    for (int mi = 0; mi < NMI; mi++)
#pragma unroll
        for (int hh = 0; hh < 2; hh++) {
            const int row = m0 + warp_m * 16 * NMI + mi * 16 + hh * 8 + gr;
#pragma unroll
            for (int ni = 0; ni < 8; ni++) {
                const int col = n0 + warp_n * 64 + ni * 8 + c2;
                float v0 = acc[mi][ni][hh * 2 + 0];
                float v1 = acc[mi][ni][hh * 2 + 1];
                if (bias) { v0 += bias[col]; v1 += bias[col + 1]; }
                const size_t off = (size_t)row * N + col;
                if (C) *(float2*)(C + off) = make_float2(v0, v1);
                if (Chi || Vth) {
                    bf16 h0 = __float2bfloat16(v0), h1 = __float2bfloat16(v1);
                    bf16 l0 = __float2bfloat16(v0 - __bfloat162float(h0));
                    bf16 l1 = __float2bfloat16(v1 - __bfloat162float(h1));
                    if (Chi) {
                        *(__nv_bfloat162*)(Chi + off) = __nv_bfloat162(h0, h1);
                        *(__nv_bfloat162*)(Clo + off) = __nv_bfloat162(l0, l1);
                    }
                    if (Vth) {  // transposed (b, c, m) layout
                        size_t toff = ((size_t)((row >> 8) * CDIM + col)) * NKV + (row & 255);
                        Vth[toff] = h0; Vth[toff + NKV] = h1;
                        Vtl[toff] = l0; Vtl[toff + NKV] = l1;
                    }
                }
            }
        }
}

// ---------------------------------------------------------------------------
// prep kernel: blocks [0, 2048) = depthwise conv + LayerNorm (512 thr = 1 ch);
// blocks [2048, ...) = fp32 -> (bf16 hi, lo) splits of x and all weights.
// ---------------------------------------------------------------------------
__device__ __forceinline__ void split4(const float* __restrict__ s, bf16* __restrict__ h,
                                       bf16* __restrict__ l, int i) {
    float4 v = ((const float4*)s)[i];
    bf16 h0 = __float2bfloat16(v.x), h1 = __float2bfloat16(v.y);
    bf16 h2 = __float2bfloat16(v.z), h3 = __float2bfloat16(v.w);
    ((__nv_bfloat162*)h)[i * 2 + 0] = __nv_bfloat162(h0, h1);
    ((__nv_bfloat162*)h)[i * 2 + 1] = __nv_bfloat162(h2, h3);
    ((__nv_bfloat162*)l)[i * 2 + 0] = __nv_bfloat162(
        __float2bfloat16(v.x - __bfloat162float(h0)),
        __float2bfloat16(v.y - __bfloat162float(h1)));
    ((__nv_bfloat162*)l)[i * 2 + 1] = __nv_bfloat162(
        __float2bfloat16(v.z - __bfloat162float(h2)),
        __float2bfloat16(v.w - __bfloat162float(h3)));
}

#define XN4 (MROW * CDIM / 4)        // 1048576
#define WN4 16384                    // RLOW*CDIM/4
#define PN4 (CDIM * CDIM / 4)        // 65536
#define SPLIT_TOT (XN4 + 6 * WN4 + PN4)
#define CONV_BLKS (NB * NKV)         // 2048
#define PREP_GRID (CONV_BLKS + (SPLIT_TOT + 511) / 512)

__global__ void __launch_bounds__(512) prep_kernel(
    const float* __restrict__ x,
    const float* __restrict__ sr_w, const float* __restrict__ sr_b,
    const float* __restrict__ ln_g, const float* __restrict__ ln_b,
    const float* __restrict__ qw1, const float* __restrict__ kw1,
    const float* __restrict__ vw1, const float* __restrict__ qw2,
    const float* __restrict__ kw2, const float* __restrict__ vw2,
    const float* __restrict__ pw,
    bf16* __restrict__ xsh, bf16* __restrict__ xsl,
    bf16* __restrict__ xh, bf16* __restrict__ xl,
    bf16* __restrict__ qw1h, bf16* __restrict__ qw1l,
    bf16* __restrict__ kvw1h, bf16* __restrict__ kvw1l,
    bf16* __restrict__ qw2h, bf16* __restrict__ qw2l,
    bf16* __restrict__ kw2h, bf16* __restrict__ kw2l,
    bf16* __restrict__ vw2h, bf16* __restrict__ vw2l,
    bf16* __restrict__ pwh, bf16* __restrict__ pwl)
{
    if (blockIdx.x < CONV_BLKS) {
        // ---- conv 2x2/s2 + bias + LayerNorm ----
        const int b = blockIdx.x >> 8, n = blockIdx.x & 255;
        const int ph = n >> 4, pw2 = n & 15, c = threadIdx.x;
        const float* xb = x + (size_t)b * NTOK * CDIM;
        const int r0 = ph * 64 + pw2 * 2;

        float val = xb[(size_t)(r0)      * CDIM + c] * sr_w[c * 4 + 0]
                  + xb[(size_t)(r0 + 1)  * CDIM + c] * sr_w[c * 4 + 1]
                  + xb[(size_t)(r0 + 32) * CDIM + c] * sr_w[c * 4 + 2]
                  + xb[(size_t)(r0 + 33) * CDIM + c] * sr_w[c * 4 + 3]
                  + sr_b[c];

        float s1 = val, s2 = val * val;
#pragma unroll
        for (int o = 16; o > 0; o >>= 1) {
            s1 += __shfl_xor_sync(0xffffffffu, s1, o);
            s2 += __shfl_xor_sync(0xffffffffu, s2, o);
        }
        __shared__ float r1[16], r2[16];
        const int w = c >> 5, lane = c & 31;
        if (lane == 0) { r1[w] = s1; r2[w] = s2; }
        __syncthreads();
        float t1 = 0.f, t2 = 0.f;
#pragma unroll
        for (int i = 0; i < 16; i++) { t1 += r1[i]; t2 += r2[i]; }
        const float mu  = t1 * (1.f / 512.f);
        const float var = t2 * (1.f / 512.f) - mu * mu;
        const float inv = rsqrtf(var + 1e-5f);
        const float o = (val - mu) * inv * ln_g[c] + ln_b[c];
        const size_t off = (size_t)(b * NKV + n) * CDIM + c;
        bf16 h = __float2bfloat16(o);
        xsh[off] = h;
        xsl[off] = __float2bfloat16(o - __bfloat162float(h));
        return;
    }

    // ---- splits ----
    int i = (blockIdx.x - CONV_BLKS) * 512 + threadIdx.x;
    if (i < XN4) { split4(x, xh, xl, i); return; }
    i -= XN4;
    if (i < 6 * WN4) {
        int j = i / WN4, off = i - j * WN4;
        switch (j) {
            case 0: split4(qw1, qw1h, qw1l, off); break;
            case 1: split4(kw1, kvw1h, kvw1l, off); break;
            case 2: split4(vw1, kvw1h + 4 * WN4, kvw1l + 4 * WN4, off); break;
            case 3: split4(qw2, qw2h, qw2l, off); break;
            case 4: split4(kw2, kw2h, kw2l, off); break;
            default: split4(vw2, vw2h, vw2l, off); break;
        }
    } else {
        int off = i - 6 * WN4;
        if (off < PN4) split4(pw, pwh, pwl, off);
    }
}

// ---------------------------------------------------------------------------
// HMMA attention: CTA = (b, h, 512 q rows as 4 subtiles of 128). 8 warps.
// K/V staged once; Q double-buffered; mask read inline as int2 (hidden).
// ---------------------------------------------------------------------------
#define AQS 72
#define AKS 72
#define AVS 264
#define QBUF(i) ((i) * 36864)
#define KH_OFF 73728
#define KL_OFF 110592
#define VH_OFF 147456
#define VL_OFF 181248
#define ATTN_SMEM 215040

__global__ void __launch_bounds__(256, 1) attn_kernel(
    const bf16* __restrict__ qh, const bf16* __restrict__ ql,
    const bf16* __restrict__ kh, const bf16* __restrict__ kl,
    const bf16* __restrict__ vth, const bf16* __restrict__ vtl,
    const int* __restrict__ mask,
    bf16* __restrict__ aoh, bf16* __restrict__ aol)
{
    extern __shared__ char smem[];
    const uint32_t sb = smem_u32(smem);
    const int qt = blockIdx.x;          // 0..1 (512 q rows each)
    const int bh = blockIdx.y;          // 0..63
    const int b = bh >> 3, h = bh & 7;
    const int tid = threadIdx.x, lane = tid & 31, wid = tid >> 5;

    const bf16* khg = kh + ((size_t)(b * NKV)) * CDIM + h * HD;
    const bf16* klg = kl + ((size_t)(b * NKV)) * CDIM + h * HD;
    const bf16* vhg = vth + ((size_t)(b * CDIM + h * HD)) * NKV;
    const bf16* vlg = vtl + ((size_t)(b * CDIM + h * HD)) * NKV;
    const bf16* qhg0 = qh + ((size_t)(b * NTOK + qt * 512)) * CDIM + h * HD;
    const bf16* qlg0 = ql + ((size_t)(b * NTOK + qt * 512)) * CDIM + h * HD;

    // stage K (256x64), Vt (64x256), Q subtile 0
#pragma unroll
    for (int i = tid; i < 2048; i += 256) {
        int r = i >> 3, c = i & 7;
        CP16(sb + KH_OFF + r * (AKS * 2) + c * 16, khg + (size_t)r * CDIM + c * 8);
        CP16(sb + KL_OFF + r * (AKS * 2) + c * 16, klg + (size_t)r * CDIM + c * 8);
    }
#pragma unroll
    for (int i = tid; i < 2048; i += 256) {
        int r = i >> 5, c = i & 31;
        CP16(sb + VH_OFF + r * (AVS * 2) + c * 16, vhg + (size_t)r * NKV + c * 8);
        CP16(sb + VL_OFF + r * (AVS * 2) + c * 16, vlg + (size_t)r * NKV + c * 8);
    }
#pragma unroll
    for (int i = tid; i < 1024; i += 256) {
        int r = i >> 3, c = i & 7;
        CP16(sb + QBUF(0) + r * (AQS * 2) + c * 16,         qhg0 + (size_t)r * CDIM + c * 8);
        CP16(sb + QBUF(0) + 18432 + r * (AQS * 2) + c * 16, qlg0 + (size_t)r * CDIM + c * 8);
    }
    CP_COMMIT();

    const int row0 = wid * 16;
    const int gr = lane >> 2, cq = (lane & 3) * 2;
    const float scale = 0.125f;

    for (int s = 0; s < 4; s++) {
        CP_WAIT0();
        __syncthreads();
        const uint32_t qb = sb + QBUF(s & 1);
        const int qrow0 = qt * 512 + s * 128;

        float acc[32][4];
#pragma unroll
        for (int na = 0; na < 32; na++)
#pragma unroll
            for (int t = 0; t < 4; t++) acc[na][t] = 0.f;

#pragma unroll
        for (int ks = 0; ks < 4; ks++) {
            uint32_t a_h[4], a_l[4];
            LDMX4(a_h, qb + ((row0 + (lane & 15)) * AQS + ks * 16 + (lane >> 4) * 8) * 2);
            LDMX4(a_l, qb + 18432 + ((row0 + (lane & 15)) * AQS + ks * 16 + (lane >> 4) * 8) * 2);
#pragma unroll
            for (int nb = 0; nb < 16; nb++) {
                uint32_t k_h[4], k_l[4];
                LDMX4(k_h, sb + KH_OFF + ((nb * 16 + (lane & 15)) * AKS + ks * 16 + (lane >> 4) * 8) * 2);
                LDMX4(k_l, sb + KL_OFF + ((nb * 16 + (lane & 15)) * AKS + ks * 16 + (lane >> 4) * 8) * 2);
                MMA(acc[2 * nb],     a_h, k_h[0], k_h[2]);
                MMA(acc[2 * nb + 1], a_h, k_h[1], k_h[3]);
                MMA(acc[2 * nb],     a_h, k_l[0], k_l[2]);
                MMA(acc[2 * nb + 1], a_h, k_l[1], k_l[3]);
                MMA(acc[2 * nb],     a_l, k_h[0], k_h[2]);
                MMA(acc[2 * nb + 1], a_l, k_h[1], k_h[3]);
            }
        }

        // prefetch next Q subtile into other buffer (overlaps softmax + PV)
        if (s < 3) {
            const bf16* nqh = qhg0 + (size_t)(s + 1) * 128 * CDIM;
            const bf16* nql = qlg0 + (size_t)(s + 1) * 128 * CDIM;
            const uint32_t nqb = sb + QBUF((s + 1) & 1);
#pragma unroll
            for (int i = tid; i < 1024; i += 256) {
                int r = i >> 3, c = i & 7;
                CP16(nqb + r * (AQS * 2) + c * 16,         nqh + (size_t)r * CDIM + c * 8);
                CP16(nqb + 18432 + r * (AQS * 2) + c * 16, nql + (size_t)r * CDIM + c * 8);
            }
            CP_COMMIT();
        }

        const int* mg0 = mask + ((size_t)bh * NTOK + qrow0 + row0 + gr) * NKV;
        const int* mg1 = mg0 + 8 * NKV;

        float mx0 = -1e30f, mx1 = -1e30f;
#pragma unroll
        for (int na = 0; na < 32; na++) {
            const int c = na * 8 + cq;
            int2 m0 = *(const int2*)(mg0 + c);
            int2 m1 = *(const int2*)(mg1 + c);
            float s0 = acc[na][0] * scale; if (m0.x) s0 = -1e30f;
            float s1 = acc[na][1] * scale; if (m0.y) s1 = -1e30f;
            float s2 = acc[na][2] * scale; if (m1.x) s2 = -1e30f;
            float s3 = acc[na][3] * scale; if (m1.y) s3 = -1e30f;
            acc[na][0] = s0; acc[na][1] = s1; acc[na][2] = s2; acc[na][3] = s3;
            mx0 = fmaxf(mx0, fmaxf(s0, s1));
            mx1 = fmaxf(mx1, fmaxf(s2, s3));
        }
        mx0 = fmaxf(mx0, __shfl_xor_sync(0xffffffffu, mx0, 1));
        mx0 = fmaxf(mx0, __shfl_xor_sync(0xffffffffu, mx0, 2));
        mx1 = fmaxf(mx1, __shfl_xor_sync(0xffffffffu, mx1, 1));
        mx1 = fmaxf(mx1, __shfl_xor_sync(0xffffffffu, mx1, 2));

        float sum0 = 0.f, sum1 = 0.f;
#pragma unroll
        for (int na = 0; na < 32; na++) {
            float e0 = __expf(acc[na][0] - mx0);
            float e1 = __expf(acc[na][1] - mx0);
            float e2 = __expf(acc[na][2] - mx1);
            float e3 = __expf(acc[na][3] - mx1);
            acc[na][0] = e0; acc[na][1] = e1; acc[na][2] = e2; acc[na][3] = e3;
            sum0 += e0 + e1; sum1 += e2 + e3;
        }
        sum0 += __shfl_xor_sync(0xffffffffu, sum0, 1);
        sum0 += __shfl_xor_sync(0xffffffffu, sum0, 2);
        sum1 += __shfl_xor_sync(0xffffffffu, sum1, 1);
        sum1 += __shfl_xor_sync(0xffffffffu, sum1, 2);

        float acco[8][4];
#pragma unroll
        for (int na = 0; na < 8; na++)
#pragma unroll
            for (int t = 0; t < 4; t++) acco[na][t] = 0.f;

#pragma unroll
        for (int t = 0; t < 16; t++) {
            uint32_t p_h[4], p_l[4];
            pack_hl(acc[2 * t][0],     acc[2 * t][1],     p_h[0], p_l[0]);
            pack_hl(acc[2 * t][2],     acc[2 * t][3],     p_h[1], p_l[1]);
            pack_hl(acc[2 * t + 1][0], acc[2 * t + 1][1], p_h[2], p_l[2]);
            pack_hl(acc[2 * t + 1][2], acc[2 * t + 1][3], p_h[3], p_l[3]);
#pragma unroll
            for (int vb = 0; vb < 4; vb++) {
                uint32_t v_h[4], v_l[4];
                LDMX4(v_h, sb + VH_OFF + ((vb * 16 + (lane & 15)) * AVS + t * 16 + (lane >> 4) * 8) * 2);
                LDMX4(v_l, sb + VL_OFF + ((vb * 16 + (lane & 15)) * AVS + t * 16 + (lane >> 4) * 8) * 2);
                MMA(acco[2 * vb],     p_h, v_h[0], v_h[2]);
                MMA(acco[2 * vb + 1], p_h, v_h[1], v_h[3]);
                MMA(acco[2 * vb],     p_h, v_l[0], v_l[2]);
                MMA(acco[2 * vb + 1], p_h, v_l[1], v_l[3]);
                MMA(acco[2 * vb],     p_l, v_h[0], v_h[2]);
                MMA(acco[2 * vb + 1], p_l, v_h[1], v_h[3]);
            }
        }

        const float i0 = 1.f / sum0, i1 = 1.f / sum1;
        const size_t rbase = ((size_t)(b * NTOK + qrow0 + row0 + gr)) * CDIM + h * HD;
#pragma unroll
        for (int na = 0; na < 8; na++) {
            const int c = na * 8 + cq;
            uint32_t h0, l0, h1, l1;
            pack_hl(acco[na][0] * i0, acco[na][1] * i0, h0, l0);
            pack_hl(acco[na][2] * i1, acco[na][3] * i1, h1, l1);
            *(uint32_t*)(aoh + rbase + c)            = h0;
            *(uint32_t*)(aol + rbase + c)            = l0;
            *(uint32_t*)(aoh + rbase + 8 * CDIM + c) = h1;
            *(uint32_t*)(aol + rbase + 8 * CDIM + c) = l1;
        }
    }
}

// ---------------------------------------------------------------------------
extern "C" void kernel_launch(void* const* d_in, const int* in_sizes, int n_in,
                              void* d_out, int out_size) {
    const float* x      = (const float*)d_in[0];
    const int*   mask   = (const int*)d_in[1];
    const float* q_w1   = (const float*)d_in[2];
    const float* q_w2   = (const float*)d_in[3];
    const float* k_w1   = (const float*)d_in[4];
    const float* k_w2   = (const float*)d_in[5];
    const float* v_w1   = (const float*)d_in[6];
    const float* v_w2   = (const float*)d_in[7];
    const float* sr_w   = (const float*)d_in[8];
    const float* sr_b   = (const float*)d_in[9];
    const float* ln_g   = (const float*)d_in[10];
    const float* ln_b   = (const float*)d_in[11];
    const float* proj_w = (const float*)d_in[12];
    const float* proj_b = (const float*)d_in[13];
    float* out = (float*)d_out;

    bf16 *xh, *xl, *qw1h, *qw1l, *kvw1h, *kvw1l;
    bf16 *qw2h, *qw2l, *kw2h, *kw2l, *vw2h, *vw2l, *pwh, *pwl;
    bf16 *qlh, *qll, *xsh, *xsl, *kvlh, *kvll;
    bf16 *q2h, *q2l, *k2h, *k2l, *vth, *vtl, *aoh, *aol;
    cudaGetSymbolAddress((void**)&xh, g_xh);       cudaGetSymbolAddress((void**)&xl, g_xl);
    cudaGetSymbolAddress((void**)&qw1h, g_qw1h);   cudaGetSymbolAddress((void**)&qw1l, g_qw1l);
    cudaGetSymbolAddress((void**)&kvw1h, g_kvw1h); cudaGetSymbolAddress((void**)&kvw1l, g_kvw1l);
    cudaGetSymbolAddress((void**)&qw2h, g_qw2h);   cudaGetSymbolAddress((void**)&qw2l, g_qw2l);
    cudaGetSymbolAddress((void**)&kw2h, g_kw2h);   cudaGetSymbolAddress((void**)&kw2l, g_kw2l);
    cudaGetSymbolAddress((void**)&vw2h, g_vw2h);   cudaGetSymbolAddress((void**)&vw2l, g_vw2l);
    cudaGetSymbolAddress((void**)&pwh, g_pwh);     cudaGetSymbolAddress((void**)&pwl, g_pwl);
    cudaGetSymbolAddress((void**)&qlh, g_qlh);     cudaGetSymbolAddress((void**)&qll, g_qll);
    cudaGetSymbolAddress((void**)&xsh, g_xsh);     cudaGetSymbolAddress((void**)&xsl, g_xsl);
    cudaGetSymbolAddress((void**)&kvlh, g_kvlh);   cudaGetSymbolAddress((void**)&kvll, g_kvll);
    cudaGetSymbolAddress((void**)&q2h, g_q2h);     cudaGetSymbolAddress((void**)&q2l, g_q2l);
    cudaGetSymbolAddress((void**)&k2h, g_k2h);     cudaGetSymbolAddress((void**)&k2l, g_k2l);
    cudaGetSymbolAddress((void**)&vth, g_vth);     cudaGetSymbolAddress((void**)&vtl, g_vtl);
    cudaGetSymbolAddress((void**)&aoh, g_aoh);     cudaGetSymbolAddress((void**)&aol, g_aol);

    constexpr int SM1 = 2 * (2 * (64 * TROWS * 2) + 2 * (128 * TROWS * 2));   // 61440
    constexpr int SM2 = 2 * (2 * (128 * TROWS * 2) + 2 * (128 * TROWS * 2));  // 81920

    static bool cfg = false;
    if (!cfg) {
        cudaFuncSetAttribute(gemm3g_kernel<1>, cudaFuncAttributeMaxDynamicSharedMemorySize, SM1);
        cudaFuncSetAttribute(gemm3g_kernel<2>, cudaFuncAttributeMaxDynamicSharedMemorySize, SM2);
        cudaFuncSetAttribute(attn_kernel, cudaFuncAttributeMaxDynamicSharedMemorySize, ATTN_SMEM);
        cfg = true;
    }

    // fused prep: conv+LN blocks + all fp32->bf16x2 splits, one launch
    prep_kernel<<<PREP_GRID, 512>>>(
        x, sr_w, sr_b, ln_g, ln_b,
        q_w1, k_w1, v_w1, q_w2, k_w2, v_w2, proj_w,
        xsh, xsl, xh, xl, qw1h, qw1l, kvw1h, kvw1l,
        qw2h, qw2l, kw2h, kw2l, vw2h, vw2l, pwh, pwl);

    // stage 1 group: q1 (128 CTAs) + kv1 (64 CTAs)
    {
        GemmGroup g = {};
        g.base1 = 128; g.base2 = 192;
        g.gx[0] = 1; g.Ah[0] = xh;  g.Al[0] = xl;  g.Bh[0] = qw1h;  g.Bl[0] = qw1l;
        g.Chi[0] = qlh;  g.Clo[0] = qll;  g.lda[0] = CDIM; g.N[0] = RLOW;    g.K[0] = CDIM;
        g.gx[1] = 2; g.Ah[1] = xsh; g.Al[1] = xsl; g.Bh[1] = kvw1h; g.Bl[1] = kvw1l;
        g.Chi[1] = kvlh; g.Clo[1] = kvll; g.lda[1] = CDIM; g.N[1] = 2 * RLOW; g.K[1] = CDIM;
        gemm3g_kernel<1><<<192, 256, SM1>>>(g);
    }

    // stage 2 group: q2 (256 CTAs) + k2 (64) + v2 (64, transposed out)
    {
        GemmGroup g = {};
        g.base1 = 256; g.base2 = 320;
        g.gx[0] = 4; g.Ah[0] = qlh; g.Al[0] = qll; g.Bh[0] = qw2h; g.Bl[0] = qw2l;
        g.Chi[0] = q2h; g.Clo[0] = q2l; g.lda[0] = RLOW; g.N[0] = CDIM; g.K[0] = RLOW;
        g.gx[1] = 4; g.Ah[1] = kvlh; g.Al[1] = kvll; g.Bh[1] = kw2h; g.Bl[1] = kw2l;
        g.Chi[1] = k2h; g.Clo[1] = k2l; g.lda[1] = 2 * RLOW; g.N[1] = CDIM; g.K[1] = RLOW;
        g.gx[2] = 4; g.Ah[2] = kvlh + RLOW; g.Al[2] = kvll + RLOW; g.Bh[2] = vw2h; g.Bl[2] = vw2l;
        g.Vth[2] = vth; g.Vtl[2] = vtl; g.lda[2] = 2 * RLOW; g.N[2] = CDIM; g.K[2] = RLOW;
        gemm3g_kernel<2><<<384, 256, SM2>>>(g);
    }

    // attention (HMMA, 4 q-subtiles per CTA, Q double-buffered, inline mask)
    attn_kernel<<<dim3(2, NB * NHEAD), 256, ATTN_SMEM>>>(q2h, q2l, k2h, k2l,
        vth, vtl, mask, aoh, aol);

    // output projection
    {
        GemmGroup g = {};
        g.base1 = 256; g.base2 = 256;
        g.gx[0] = 4; g.Ah[0] = aoh; g.Al[0] = aol; g.Bh[0] = pwh; g.Bl[0] = pwl;
        g.C[0] = out; g.bias[0] = proj_b; g.lda[0] = CDIM; g.N[0] = CDIM; g.K[0] = CDIM;
        gemm3g_kernel<2><<<256, 256, SM2>>>(g);
    }
}

// round 16
// speedup vs baseline: 1.1955x; 1.0185x over previous
#include <cuda_runtime.h>
#include <cuda_bf16.h>
#include <math.h>
#include <stdint.h>

// ---------------------------------------------------------------------------
// changeAttention on GB300 (plain sm_103 -> mma.sync HMMA).
// bf16x3 split grouped GEMMs + bf16x3 HMMA attention with ONLINE softmax
// (KV chunked 2x128 -> halves score-accumulator register pressure).
//   B=8, N=1024, C=512, heads=8, d=64, r=128, SR=2 -> Nn=256
// ---------------------------------------------------------------------------

#define NB    8
#define NTOK  1024
#define CDIM  512
#define NHEAD 8
#define HD    64
#define RLOW  128
#define NKV   256
#define MROW  (NB * NTOK)   // 8192
#define MKV   (NB * NKV)    // 2048

typedef __nv_bfloat16 bf16;

// ---------------- scratch (device globals) ----------------
__device__ __align__(128) bf16 g_xh  [MROW * CDIM],      g_xl  [MROW * CDIM];
__device__ __align__(128) bf16 g_qw1h[RLOW * CDIM],      g_qw1l[RLOW * CDIM];
__device__ __align__(128) bf16 g_kvw1h[2 * RLOW * CDIM], g_kvw1l[2 * RLOW * CDIM];
__device__ __align__(128) bf16 g_qw2h[CDIM * RLOW],      g_qw2l[CDIM * RLOW];
__device__ __align__(128) bf16 g_kw2h[CDIM * RLOW],      g_kw2l[CDIM * RLOW];
__device__ __align__(128) bf16 g_vw2h[CDIM * RLOW],      g_vw2l[CDIM * RLOW];
__device__ __align__(128) bf16 g_pwh [CDIM * CDIM],      g_pwl [CDIM * CDIM];
__device__ __align__(128) bf16 g_qlh [MROW * RLOW],      g_qll [MROW * RLOW];
__device__ __align__(128) bf16 g_xsh [MKV  * CDIM],      g_xsl [MKV  * CDIM];
__device__ __align__(128) bf16 g_kvlh[MKV * 2 * RLOW],   g_kvll[MKV * 2 * RLOW];
__device__ __align__(128) bf16 g_q2h [MROW * CDIM],      g_q2l [MROW * CDIM];
__device__ __align__(128) bf16 g_k2h [MKV  * CDIM],      g_k2l [MKV  * CDIM];
__device__ __align__(128) bf16 g_vth [MKV  * CDIM],      g_vtl [MKV  * CDIM];  // (b,c,m)
__device__ __align__(128) bf16 g_aoh [MROW * CDIM],      g_aol [MROW * CDIM];

// ---------------- PTX helpers ----------------
__device__ __forceinline__ uint32_t smem_u32(const void* p) {
    uint32_t a;
    asm("{ .reg .u64 t; cvta.to.shared.u64 t, %1; cvt.u32.u64 %0, t; }" : "=r"(a) : "l"(p));
    return a;
}
#define CP16(d, s)   asm volatile("cp.async.ca.shared.global [%0], [%1], 16;" :: "r"(d), "l"(s))
#define CP_COMMIT()  asm volatile("cp.async.commit_group;" ::: "memory")
#define CP_WAIT1()   asm volatile("cp.async.wait_group 1;" ::: "memory")
#define CP_WAIT0()   asm volatile("cp.async.wait_group 0;" ::: "memory")

#define LDMX4(r, addr)                                                         \
    asm volatile("ldmatrix.sync.aligned.m8n8.x4.shared.b16 {%0,%1,%2,%3}, [%4];" \
        : "=r"((r)[0]), "=r"((r)[1]), "=r"((r)[2]), "=r"((r)[3]) : "r"(addr))

#define MMA(d, a, b0, b1)                                                      \
    asm volatile("mma.sync.aligned.m16n8k16.row.col.f32.bf16.bf16.f32 "        \
        "{%0,%1,%2,%3},{%4,%5,%6,%7},{%8,%9},{%0,%1,%2,%3};"                   \
        : "+f"((d)[0]), "+f"((d)[1]), "+f"((d)[2]), "+f"((d)[3])               \
        : "r"((a)[0]), "r"((a)[1]), "r"((a)[2]), "r"((a)[3]), "r"(b0), "r"(b1))

__device__ __forceinline__ void pack_hl(float a, float b, uint32_t& h, uint32_t& l) {
    __nv_bfloat162 hh = __floats2bfloat162_rn(a, b);
    h = *reinterpret_cast<uint32_t*>(&hh);
    __nv_bfloat162 ll = __floats2bfloat162_rn(a - __bfloat162float(hh.x),
                                              b - __bfloat162float(hh.y));
    l = *reinterpret_cast<uint32_t*>(&ll);
}

// ---------------------------------------------------------------------------
// Grouped bf16x3 GEMM: up to 3 problems per launch, linear CTA decode.
// ---------------------------------------------------------------------------
#define TROWS 40

struct GemmGroup {
    int base1, base2;
    int gx[3];
    const bf16 *Ah[3], *Al[3], *Bh[3], *Bl[3];
    bf16 *Chi[3], *Clo[3], *Vth[3], *Vtl[3];
    float *C[3];
    const float *bias[3];
    int lda[3], N[3], K[3];
};

template<int NMI>
__device__ __forceinline__ void stage_loadT(
    const bf16* __restrict__ Ah, const bf16* __restrict__ Al, int lda,
    const bf16* __restrict__ Bh, const bf16* __restrict__ Bl,
    int m0, int n0, int K, int k0, uint32_t st, int tid)
{
    constexpr int ATB = 64 * NMI * TROWS * 2;
    constexpr int BTB = 128 * TROWS * 2;
    const bf16* a0 = Ah + (size_t)m0 * lda + k0;
    const bf16* a1 = Al + (size_t)m0 * lda + k0;
    const bf16* b0 = Bh + (size_t)n0 * K + k0;
    const bf16* b1 = Bl + (size_t)n0 * K + k0;
#pragma unroll
    for (int i = tid; i < 64 * NMI * 4; i += 256) {
        int r = i >> 2, c = i & 3;
        CP16(st + r * 80 + c * 16,       a0 + (size_t)r * lda + c * 8);
        CP16(st + ATB + r * 80 + c * 16, a1 + (size_t)r * lda + c * 8);
    }
#pragma unroll
    for (int i = tid; i < 512; i += 256) {
        int r = i >> 2, c = i & 3;
        CP16(st + 2 * ATB + r * 80 + c * 16,       b0 + (size_t)r * K + c * 8);
        CP16(st + 2 * ATB + BTB + r * 80 + c * 16, b1 + (size_t)r * K + c * 8);
    }
}

__device__ __forceinline__ uint32_t frag_addr(uint32_t tile, int row0, int kstep, int lane) {
    return tile + ((row0 + (lane & 15)) * TROWS + kstep * 16 + (lane >> 4) * 8) * 2;
}

template<int NMI>
__global__ void __launch_bounds__(256, 2) gemm3g_kernel(GemmGroup g)
{
    constexpr int ATB = 64 * NMI * TROWS * 2;
    constexpr int BTB = 128 * TROWS * 2;
    constexpr int STB = 2 * ATB + 2 * BTB;
    extern __shared__ char smem[];
    const uint32_t sb = smem_u32(smem);
    const int tid = threadIdx.x, lane = tid & 31, wid = tid >> 5;
    const int warp_m = wid >> 1, warp_n = wid & 1;

    const int cta = blockIdx.x;
    const int p = (cta >= g.base1) + (cta >= g.base2);
    const int local = cta - (p == 2 ? g.base2 : (p == 1 ? g.base1 : 0));
    const int gx = g.gx[p];
    const int m0 = (local / gx) * (64 * NMI), n0 = (local % gx) * 128;
    const bf16 *Ah = g.Ah[p], *Al = g.Al[p], *Bh = g.Bh[p], *Bl = g.Bl[p];
    const int lda = g.lda[p], N = g.N[p], K = g.K[p];
    const int nch = K >> 5;

    float acc[NMI][8][4];
#pragma unroll
    for (int i = 0; i < NMI; i++)
#pragma unroll
        for (int j = 0; j < 8; j++)
#pragma unroll
            for (int t = 0; t < 4; t++) acc[i][j][t] = 0.f;

    stage_loadT<NMI>(Ah, Al, lda, Bh, Bl, m0, n0, K, 0, sb, tid);
    CP_COMMIT();

    for (int ch = 0; ch < nch; ch++) {
        if (ch + 1 < nch) {
            stage_loadT<NMI>(Ah, Al, lda, Bh, Bl, m0, n0, K, (ch + 1) << 5,
                             sb + ((ch + 1) & 1) * STB, tid);
            CP_COMMIT();
            CP_WAIT1();
        } else {
            CP_WAIT0();
        }
        __syncthreads();

        const uint32_t st = sb + (ch & 1) * STB;
#pragma unroll
        for (int ks = 0; ks < 2; ks++) {
            uint32_t ah[NMI][4], al[NMI][4], bh[4][4], bl[4][4];
#pragma unroll
            for (int mi = 0; mi < NMI; mi++) {
                LDMX4(ah[mi], frag_addr(st,       warp_m * 16 * NMI + mi * 16, ks, lane));
                LDMX4(al[mi], frag_addr(st + ATB, warp_m * 16 * NMI + mi * 16, ks, lane));
            }
#pragma unroll
            for (int q = 0; q < 4; q++) {
                LDMX4(bh[q], frag_addr(st + 2 * ATB,       warp_n * 64 + q * 16, ks, lane));
                LDMX4(bl[q], frag_addr(st + 2 * ATB + BTB, warp_n * 64 + q * 16, ks, lane));
            }
#pragma unroll
            for (int mi = 0; mi < NMI; mi++)
#pragma unroll
                for (int q = 0; q < 4; q++) {
                    MMA(acc[mi][2 * q],     ah[mi], bh[q][0], bh[q][2]);
                    MMA(acc[mi][2 * q + 1], ah[mi], bh[q][1], bh[q][3]);
                    MMA(acc[mi][2 * q],     ah[mi], bl[q][0], bl[q][2]);
                    MMA(acc[mi][2 * q + 1], ah[mi], bl[q][1], bl[q][3]);
                    MMA(acc[mi][2 * q],     al[mi], bh[q][0], bh[q][2]);
                    MMA(acc[mi][2 * q + 1], al[mi], bh[q][1], bh[q][3]);
                }
        }
        __syncthreads();
    }

    float* C = g.C[p];
    bf16 *Chi = g.Chi[p], *Clo = g.Clo[p], *Vth = g.Vth[p], *Vtl = g.Vtl[p];
    const float* bias = g.bias[p];
    const int gr = lane >> 2, c2 = (lane & 3) * 2;
#pragma unroll
    for (int mi = 0; mi < NMI; mi++)
#pragma unroll
        for (int hh = 0; hh < 2; hh++) {
            const int row = m0 + warp_m * 16 * NMI + mi * 16 + hh * 8 + gr;
#pragma unroll
            for (int ni = 0; ni < 8; ni++) {
                const int col = n0 + warp_n * 64 + ni * 8 + c2;
                float v0 = acc[mi][ni][hh * 2 + 0];
                float v1 = acc[mi][ni][hh * 2 + 1];
                if (bias) { v0 += bias[col]; v1 += bias[col + 1]; }
                const size_t off = (size_t)row * N + col;
                if (C) *(float2*)(C + off) = make_float2(v0, v1);
                if (Chi || Vth) {
                    bf16 h0 = __float2bfloat16(v0), h1 = __float2bfloat16(v1);
                    bf16 l0 = __float2bfloat16(v0 - __bfloat162float(h0));
                    bf16 l1 = __float2bfloat16(v1 - __bfloat162float(h1));
                    if (Chi) {
                        *(__nv_bfloat162*)(Chi + off) = __nv_bfloat162(h0, h1);
                        *(__nv_bfloat162*)(Clo + off) = __nv_bfloat162(l0, l1);
                    }
                    if (Vth) {  // transposed (b, c, m) layout
                        size_t toff = ((size_t)((row >> 8) * CDIM + col)) * NKV + (row & 255);
                        Vth[toff] = h0; Vth[toff + NKV] = h1;
                        Vtl[toff] = l0; Vtl[toff + NKV] = l1;
                    }
                }
            }
        }
}

// ---------------------------------------------------------------------------
// prep kernel: blocks [0, 2048) = depthwise conv + LayerNorm (512 thr = 1 ch);
// blocks [2048, ...) = fp32 -> (bf16 hi, lo) splits of x and all weights.
// ---------------------------------------------------------------------------
__device__ __forceinline__ void split4(const float* __restrict__ s, bf16* __restrict__ h,
                                       bf16* __restrict__ l, int i) {
    float4 v = ((const float4*)s)[i];
    bf16 h0 = __float2bfloat16(v.x), h1 = __float2bfloat16(v.y);
    bf16 h2 = __float2bfloat16(v.z), h3 = __float2bfloat16(v.w);
    ((__nv_bfloat162*)h)[i * 2 + 0] = __nv_bfloat162(h0, h1);
    ((__nv_bfloat162*)h)[i * 2 + 1] = __nv_bfloat162(h2, h3);
    ((__nv_bfloat162*)l)[i * 2 + 0] = __nv_bfloat162(
        __float2bfloat16(v.x - __bfloat162float(h0)),
        __float2bfloat16(v.y - __bfloat162float(h1)));
    ((__nv_bfloat162*)l)[i * 2 + 1] = __nv_bfloat162(
        __float2bfloat16(v.z - __bfloat162float(h2)),
        __float2bfloat16(v.w - __bfloat162float(h3)));
}

#define XN4 (MROW * CDIM / 4)        // 1048576
#define WN4 16384                    // RLOW*CDIM/4
#define PN4 (CDIM * CDIM / 4)        // 65536
#define SPLIT_TOT (XN4 + 6 * WN4 + PN4)
#define CONV_BLKS (NB * NKV)         // 2048
#define PREP_GRID (CONV_BLKS + (SPLIT_TOT + 511) / 512)

__global__ void __launch_bounds__(512) prep_kernel(
    const float* __restrict__ x,
    const float* __restrict__ sr_w, const float* __restrict__ sr_b,
    const float* __restrict__ ln_g, const float* __restrict__ ln_b,
    const float* __restrict__ qw1, const float* __restrict__ kw1,
    const float* __restrict__ vw1, const float* __restrict__ qw2,
    const float* __restrict__ kw2, const float* __restrict__ vw2,
    const float* __restrict__ pw,
    bf16* __restrict__ xsh, bf16* __restrict__ xsl,
    bf16* __restrict__ xh, bf16* __restrict__ xl,
    bf16* __restrict__ qw1h, bf16* __restrict__ qw1l,
    bf16* __restrict__ kvw1h, bf16* __restrict__ kvw1l,
    bf16* __restrict__ qw2h, bf16* __restrict__ qw2l,
    bf16* __restrict__ kw2h, bf16* __restrict__ kw2l,
    bf16* __restrict__ vw2h, bf16* __restrict__ vw2l,
    bf16* __restrict__ pwh, bf16* __restrict__ pwl)
{
    if (blockIdx.x < CONV_BLKS) {
        const int b = blockIdx.x >> 8, n = blockIdx.x & 255;
        const int ph = n >> 4, pw2 = n & 15, c = threadIdx.x;
        const float* xb = x + (size_t)b * NTOK * CDIM;
        const int r0 = ph * 64 + pw2 * 2;

        float val = xb[(size_t)(r0)      * CDIM + c] * sr_w[c * 4 + 0]
                  + xb[(size_t)(r0 + 1)  * CDIM + c] * sr_w[c * 4 + 1]
                  + xb[(size_t)(r0 + 32) * CDIM + c] * sr_w[c * 4 + 2]
                  + xb[(size_t)(r0 + 33) * CDIM + c] * sr_w[c * 4 + 3]
                  + sr_b[c];

        float s1 = val, s2 = val * val;
#pragma unroll
        for (int o = 16; o > 0; o >>= 1) {
            s1 += __shfl_xor_sync(0xffffffffu, s1, o);
            s2 += __shfl_xor_sync(0xffffffffu, s2, o);
        }
        __shared__ float r1[16], r2[16];
        const int w = c >> 5, lane = c & 31;
        if (lane == 0) { r1[w] = s1; r2[w] = s2; }
        __syncthreads();
        float t1 = 0.f, t2 = 0.f;
#pragma unroll
        for (int i = 0; i < 16; i++) { t1 += r1[i]; t2 += r2[i]; }
        const float mu  = t1 * (1.f / 512.f);
        const float var = t2 * (1.f / 512.f) - mu * mu;
        const float inv = rsqrtf(var + 1e-5f);
        const float o = (val - mu) * inv * ln_g[c] + ln_b[c];
        const size_t off = (size_t)(b * NKV + n) * CDIM + c;
        bf16 h = __float2bfloat16(o);
        xsh[off] = h;
        xsl[off] = __float2bfloat16(o - __bfloat162float(h));
        return;
    }

    int i = (blockIdx.x - CONV_BLKS) * 512 + threadIdx.x;
    if (i < XN4) { split4(x, xh, xl, i); return; }
    i -= XN4;
    if (i < 6 * WN4) {
        int j = i / WN4, off = i - j * WN4;
        switch (j) {
            case 0: split4(qw1, qw1h, qw1l, off); break;
            case 1: split4(kw1, kvw1h, kvw1l, off); break;
            case 2: split4(vw1, kvw1h + 4 * WN4, kvw1l + 4 * WN4, off); break;
            case 3: split4(qw2, qw2h, qw2l, off); break;
            case 4: split4(kw2, kw2h, kw2l, off); break;
            default: split4(vw2, vw2h, vw2l, off); break;
        }
    } else {
        int off = i - 6 * WN4;
        if (off < PN4) split4(pw, pwh, pwl, off);
    }
}

// ---------------------------------------------------------------------------
// HMMA attention, ONLINE softmax: CTA = (b,h, 512 q rows as 4 subtiles of 128).
// Per subtile, KV processed in 2 chunks of 128 cols with running (max,sum);
// score accumulator is 16 atoms (64 regs) instead of 32 (128) -> no spills.
// ---------------------------------------------------------------------------
#define AQS 72
#define AKS 72
#define AVS 264
#define QBUF(i) ((i) * 36864)
#define KH_OFF 73728
#define KL_OFF 110592
#define VH_OFF 147456
#define VL_OFF 181248
#define ATTN_SMEM 215040

__global__ void __launch_bounds__(256, 1) attn_kernel(
    const bf16* __restrict__ qh, const bf16* __restrict__ ql,
    const bf16* __restrict__ kh, const bf16* __restrict__ kl,
    const bf16* __restrict__ vth, const bf16* __restrict__ vtl,
    const int* __restrict__ mask,
    bf16* __restrict__ aoh, bf16* __restrict__ aol)
{
    extern __shared__ char smem[];
    const uint32_t sb = smem_u32(smem);
    const int qt = blockIdx.x;          // 0..1 (512 q rows each)
    const int bh = blockIdx.y;          // 0..63
    const int b = bh >> 3, h = bh & 7;
    const int tid = threadIdx.x, lane = tid & 31, wid = tid >> 5;

    const bf16* khg = kh + ((size_t)(b * NKV)) * CDIM + h * HD;
    const bf16* klg = kl + ((size_t)(b * NKV)) * CDIM + h * HD;
    const bf16* vhg = vth + ((size_t)(b * CDIM + h * HD)) * NKV;
    const bf16* vlg = vtl + ((size_t)(b * CDIM + h * HD)) * NKV;
    const bf16* qhg0 = qh + ((size_t)(b * NTOK + qt * 512)) * CDIM + h * HD;
    const bf16* qlg0 = ql + ((size_t)(b * NTOK + qt * 512)) * CDIM + h * HD;

    // stage K (256x64), Vt (64x256), Q subtile 0
#pragma unroll
    for (int i = tid; i < 2048; i += 256) {
        int r = i >> 3, c = i & 7;
        CP16(sb + KH_OFF + r * (AKS * 2) + c * 16, khg + (size_t)r * CDIM + c * 8);
        CP16(sb + KL_OFF + r * (AKS * 2) + c * 16, klg + (size_t)r * CDIM + c * 8);
    }
#pragma unroll
    for (int i = tid; i < 2048; i += 256) {
        int r = i >> 5, c = i & 31;
        CP16(sb + VH_OFF + r * (AVS * 2) + c * 16, vhg + (size_t)r * NKV + c * 8);
        CP16(sb + VL_OFF + r * (AVS * 2) + c * 16, vlg + (size_t)r * NKV + c * 8);
    }
#pragma unroll
    for (int i = tid; i < 1024; i += 256) {
        int r = i >> 3, c = i & 7;
        CP16(sb + QBUF(0) + r * (AQS * 2) + c * 16,         qhg0 + (size_t)r * CDIM + c * 8);
        CP16(sb + QBUF(0) + 18432 + r * (AQS * 2) + c * 16, qlg0 + (size_t)r * CDIM + c * 8);
    }
    CP_COMMIT();

    const int row0 = wid * 16;
    const int gr = lane >> 2, cq = (lane & 3) * 2;
    const float scale = 0.125f;

    for (int s = 0; s < 4; s++) {
        CP_WAIT0();
        __syncthreads();
        const uint32_t qb = sb + QBUF(s & 1);
        const int qrow0 = qt * 512 + s * 128;

        const int* mg0 = mask + ((size_t)bh * NTOK + qrow0 + row0 + gr) * NKV;
        const int* mg1 = mg0 + 8 * NKV;

        float m0 = -1e30f, m1 = -1e30f, sum0 = 0.f, sum1 = 0.f;
        float acco[8][4];
#pragma unroll
        for (int na = 0; na < 8; na++)
#pragma unroll
            for (int t = 0; t < 4; t++) acco[na][t] = 0.f;

#pragma unroll
        for (int ch = 0; ch < 2; ch++) {
            // --- QK^T for this 128-col chunk ---
            float acc[16][4];
#pragma unroll
            for (int na = 0; na < 16; na++)
#pragma unroll
                for (int t = 0; t < 4; t++) acc[na][t] = 0.f;

#pragma unroll
            for (int ks = 0; ks < 4; ks++) {
                uint32_t a_h[4], a_l[4];
                LDMX4(a_h, qb + ((row0 + (lane & 15)) * AQS + ks * 16 + (lane >> 4) * 8) * 2);
                LDMX4(a_l, qb + 18432 + ((row0 + (lane & 15)) * AQS + ks * 16 + (lane >> 4) * 8) * 2);
#pragma unroll
                for (int nb = 0; nb < 8; nb++) {
                    const int nbg = ch * 8 + nb;
                    uint32_t k_h[4], k_l[4];
                    LDMX4(k_h, sb + KH_OFF + ((nbg * 16 + (lane & 15)) * AKS + ks * 16 + (lane >> 4) * 8) * 2);
                    LDMX4(k_l, sb + KL_OFF + ((nbg * 16 + (lane & 15)) * AKS + ks * 16 + (lane >> 4) * 8) * 2);
                    MMA(acc[2 * nb],     a_h, k_h[0], k_h[2]);
                    MMA(acc[2 * nb + 1], a_h, k_h[1], k_h[3]);
                    MMA(acc[2 * nb],     a_h, k_l[0], k_l[2]);
                    MMA(acc[2 * nb + 1], a_h, k_l[1], k_l[3]);
                    MMA(acc[2 * nb],     a_l, k_h[0], k_h[2]);
                    MMA(acc[2 * nb + 1], a_l, k_h[1], k_h[3]);
                }
            }

            // prefetch next Q subtile once per subtile (after chunk 0 QK)
            if (ch == 0 && s < 3) {
                const bf16* nqh = qhg0 + (size_t)(s + 1) * 128 * CDIM;
                const bf16* nql = qlg0 + (size_t)(s + 1) * 128 * CDIM;
                const uint32_t nqb = sb + QBUF((s + 1) & 1);
#pragma unroll
                for (int i = tid; i < 1024; i += 256) {
                    int r = i >> 3, c = i & 7;
                    CP16(nqb + r * (AQS * 2) + c * 16,         nqh + (size_t)r * CDIM + c * 8);
                    CP16(nqb + 18432 + r * (AQS * 2) + c * 16, nql + (size_t)r * CDIM + c * 8);
                }
                CP_COMMIT();
            }

            // --- mask + chunk max ---
            float cm0 = -1e30f, cm1 = -1e30f;
#pragma unroll
            for (int na = 0; na < 16; na++) {
                const int c = ch * 128 + na * 8 + cq;
                int2 w0 = *(const int2*)(mg0 + c);
                int2 w1 = *(const int2*)(mg1 + c);
                float s0 = acc[na][0] * scale; if (w0.x) s0 = -1e30f;
                float s1 = acc[na][1] * scale; if (w0.y) s1 = -1e30f;
                float s2 = acc[na][2] * scale; if (w1.x) s2 = -1e30f;
                float s3 = acc[na][3] * scale; if (w1.y) s3 = -1e30f;
                acc[na][0] = s0; acc[na][1] = s1; acc[na][2] = s2; acc[na][3] = s3;
                cm0 = fmaxf(cm0, fmaxf(s0, s1));
                cm1 = fmaxf(cm1, fmaxf(s2, s3));
            }
            cm0 = fmaxf(cm0, __shfl_xor_sync(0xffffffffu, cm0, 1));
            cm0 = fmaxf(cm0, __shfl_xor_sync(0xffffffffu, cm0, 2));
            cm1 = fmaxf(cm1, __shfl_xor_sync(0xffffffffu, cm1, 1));
            cm1 = fmaxf(cm1, __shfl_xor_sync(0xffffffffu, cm1, 2));

            // --- online rescale ---
            const float nm0 = fmaxf(m0, cm0), nm1 = fmaxf(m1, cm1);
            const float sc0 = __expf(m0 - nm0), sc1 = __expf(m1 - nm1);
            m0 = nm0; m1 = nm1;

            float s0c = 0.f, s1c = 0.f;
#pragma unroll
            for (int na = 0; na < 16; na++) {
                float e0 = __expf(acc[na][0] - m0);
                float e1 = __expf(acc[na][1] - m0);
                float e2 = __expf(acc[na][2] - m1);
                float e3 = __expf(acc[na][3] - m1);
                acc[na][0] = e0; acc[na][1] = e1; acc[na][2] = e2; acc[na][3] = e3;
                s0c += e0 + e1; s1c += e2 + e3;
            }
            s0c += __shfl_xor_sync(0xffffffffu, s0c, 1);
            s0c += __shfl_xor_sync(0xffffffffu, s0c, 2);
            s1c += __shfl_xor_sync(0xffffffffu, s1c, 1);
            s1c += __shfl_xor_sync(0xffffffffu, s1c, 2);
            sum0 = sum0 * sc0 + s0c;
            sum1 = sum1 * sc1 + s1c;

#pragma unroll
            for (int na = 0; na < 8; na++) {
                acco[na][0] *= sc0; acco[na][1] *= sc0;
                acco[na][2] *= sc1; acco[na][3] *= sc1;
            }

            // --- P @ Vt for this chunk ---
#pragma unroll
            for (int t = 0; t < 8; t++) {
                uint32_t p_h[4], p_l[4];
                pack_hl(acc[2 * t][0],     acc[2 * t][1],     p_h[0], p_l[0]);
                pack_hl(acc[2 * t][2],     acc[2 * t][3],     p_h[1], p_l[1]);
                pack_hl(acc[2 * t + 1][0], acc[2 * t + 1][1], p_h[2], p_l[2]);
                pack_hl(acc[2 * t + 1][2], acc[2 * t + 1][3], p_h[3], p_l[3]);
#pragma unroll
                for (int vb = 0; vb < 4; vb++) {
                    uint32_t v_h[4], v_l[4];
                    LDMX4(v_h, sb + VH_OFF + ((vb * 16 + (lane & 15)) * AVS + ch * 128 + t * 16 + (lane >> 4) * 8) * 2);
                    LDMX4(v_l, sb + VL_OFF + ((vb * 16 + (lane & 15)) * AVS + ch * 128 + t * 16 + (lane >> 4) * 8) * 2);
                    MMA(acco[2 * vb],     p_h, v_h[0], v_h[2]);
                    MMA(acco[2 * vb + 1], p_h, v_h[1], v_h[3]);
                    MMA(acco[2 * vb],     p_h, v_l[0], v_l[2]);
                    MMA(acco[2 * vb + 1], p_h, v_l[1], v_l[3]);
                    MMA(acco[2 * vb],     p_l, v_h[0], v_h[2]);
                    MMA(acco[2 * vb + 1], p_l, v_h[1], v_h[3]);
                }
            }
        }

        const float i0 = 1.f / sum0, i1 = 1.f / sum1;
        const size_t rbase = ((size_t)(b * NTOK + qrow0 + row0 + gr)) * CDIM + h * HD;
#pragma unroll
        for (int na = 0; na < 8; na++) {
            const int c = na * 8 + cq;
            uint32_t h0, l0, h1, l1;
            pack_hl(acco[na][0] * i0, acco[na][1] * i0, h0, l0);
            pack_hl(acco[na][2] * i1, acco[na][3] * i1, h1, l1);
            *(uint32_t*)(aoh + rbase + c)            = h0;
            *(uint32_t*)(aol + rbase + c)            = l0;
            *(uint32_t*)(aoh + rbase + 8 * CDIM + c) = h1;
            *(uint32_t*)(aol + rbase + 8 * CDIM + c) = l1;
        }
    }
}

// ---------------------------------------------------------------------------
extern "C" void kernel_launch(void* const* d_in, const int* in_sizes, int n_in,
                              void* d_out, int out_size) {
    const float* x      = (const float*)d_in[0];
    const int*   mask   = (const int*)d_in[1];
    const float* q_w1   = (const float*)d_in[2];
    const float* q_w2   = (const float*)d_in[3];
    const float* k_w1   = (const float*)d_in[4];
    const float* k_w2   = (const float*)d_in[5];
    const float* v_w1   = (const float*)d_in[6];
    const float* v_w2   = (const float*)d_in[7];
    const float* sr_w   = (const float*)d_in[8];
    const float* sr_b   = (const float*)d_in[9];
    const float* ln_g   = (const float*)d_in[10];
    const float* ln_b   = (const float*)d_in[11];
    const float* proj_w = (const float*)d_in[12];
    const float* proj_b = (const float*)d_in[13];
    float* out = (float*)d_out;

    bf16 *xh, *xl, *qw1h, *qw1l, *kvw1h, *kvw1l;
    bf16 *qw2h, *qw2l, *kw2h, *kw2l, *vw2h, *vw2l, *pwh, *pwl;
    bf16 *qlh, *qll, *xsh, *xsl, *kvlh, *kvll;
    bf16 *q2h, *q2l, *k2h, *k2l, *vth, *vtl, *aoh, *aol;
    cudaGetSymbolAddress((void**)&xh, g_xh);       cudaGetSymbolAddress((void**)&xl, g_xl);
    cudaGetSymbolAddress((void**)&qw1h, g_qw1h);   cudaGetSymbolAddress((void**)&qw1l, g_qw1l);
    cudaGetSymbolAddress((void**)&kvw1h, g_kvw1h); cudaGetSymbolAddress((void**)&kvw1l, g_kvw1l);
    cudaGetSymbolAddress((void**)&qw2h, g_qw2h);   cudaGetSymbolAddress((void**)&qw2l, g_qw2l);
    cudaGetSymbolAddress((void**)&kw2h, g_kw2h);   cudaGetSymbolAddress((void**)&kw2l, g_kw2l);
    cudaGetSymbolAddress((void**)&vw2h, g_vw2h);   cudaGetSymbolAddress((void**)&vw2l, g_vw2l);
    cudaGetSymbolAddress((void**)&pwh, g_pwh);     cudaGetSymbolAddress((void**)&pwl, g_pwl);
    cudaGetSymbolAddress((void**)&qlh, g_qlh);     cudaGetSymbolAddress((void**)&qll, g_qll);
    cudaGetSymbolAddress((void**)&xsh, g_xsh);     cudaGetSymbolAddress((void**)&xsl, g_xsl);
    cudaGetSymbolAddress((void**)&kvlh, g_kvlh);   cudaGetSymbolAddress((void**)&kvll, g_kvll);
    cudaGetSymbolAddress((void**)&q2h, g_q2h);     cudaGetSymbolAddress((void**)&q2l, g_q2l);
    cudaGetSymbolAddress((void**)&k2h, g_k2h);     cudaGetSymbolAddress((void**)&k2l, g_k2l);
    cudaGetSymbolAddress((void**)&vth, g_vth);     cudaGetSymbolAddress((void**)&vtl, g_vtl);
    cudaGetSymbolAddress((void**)&aoh, g_aoh);     cudaGetSymbolAddress((void**)&aol, g_aol);

    constexpr int SM1 = 2 * (2 * (64 * TROWS * 2) + 2 * (128 * TROWS * 2));   // 61440
    constexpr int SM2 = 2 * (2 * (128 * TROWS * 2) + 2 * (128 * TROWS * 2));  // 81920

    static bool cfg = false;
    if (!cfg) {
        cudaFuncSetAttribute(gemm3g_kernel<1>, cudaFuncAttributeMaxDynamicSharedMemorySize, SM1);
        cudaFuncSetAttribute(gemm3g_kernel<2>, cudaFuncAttributeMaxDynamicSharedMemorySize, SM2);
        cudaFuncSetAttribute(attn_kernel, cudaFuncAttributeMaxDynamicSharedMemorySize, ATTN_SMEM);
        cfg = true;
    }

    // fused prep: conv+LN blocks + all fp32->bf16x2 splits, one launch
    prep_kernel<<<PREP_GRID, 512>>>(
        x, sr_w, sr_b, ln_g, ln_b,
        q_w1, k_w1, v_w1, q_w2, k_w2, v_w2, proj_w,
        xsh, xsl, xh, xl, qw1h, qw1l, kvw1h, kvw1l,
        qw2h, qw2l, kw2h, kw2l, vw2h, vw2l, pwh, pwl);

    // stage 1 group: q1 (128 CTAs) + kv1 (64 CTAs)
    {
        GemmGroup g = {};
        g.base1 = 128; g.base2 = 192;
        g.gx[0] = 1; g.Ah[0] = xh;  g.Al[0] = xl;  g.Bh[0] = qw1h;  g.Bl[0] = qw1l;
        g.Chi[0] = qlh;  g.Clo[0] = qll;  g.lda[0] = CDIM; g.N[0] = RLOW;    g.K[0] = CDIM;
        g.gx[1] = 2; g.Ah[1] = xsh; g.Al[1] = xsl; g.Bh[1] = kvw1h; g.Bl[1] = kvw1l;
        g.Chi[1] = kvlh; g.Clo[1] = kvll; g.lda[1] = CDIM; g.N[1] = 2 * RLOW; g.K[1] = CDIM;
        gemm3g_kernel<1><<<192, 256, SM1>>>(g);
    }

    // stage 2 group: q2 (256 CTAs) + k2 (64) + v2 (64, transposed out)
    {
        GemmGroup g = {};
        g.base1 = 256; g.base2 = 320;
        g.gx[0] = 4; g.Ah[0] = qlh; g.Al[0] = qll; g.Bh[0] = qw2h; g.Bl[0] = qw2l;
        g.Chi[0] = q2h; g.Clo[0] = q2l; g.lda[0] = RLOW; g.N[0] = CDIM; g.K[0] = RLOW;
        g.gx[1] = 4; g.Ah[1] = kvlh; g.Al[1] = kvll; g.Bh[1] = kw2h; g.Bl[1] = kw2l;
        g.Chi[1] = k2h; g.Clo[1] = k2l; g.lda[1] = 2 * RLOW; g.N[1] = CDIM; g.K[1] = RLOW;
        g.gx[2] = 4; g.Ah[2] = kvlh + RLOW; g.Al[2] = kvll + RLOW; g.Bh[2] = vw2h; g.Bl[2] = vw2l;
        g.Vth[2] = vth; g.Vtl[2] = vtl; g.lda[2] = 2 * RLOW; g.N[2] = CDIM; g.K[2] = RLOW;
        gemm3g_kernel<2><<<384, 256, SM2>>>(g);
    }

    // attention (HMMA, online softmax, 4 q-subtiles per CTA, Q double-buffered)
    attn_kernel<<<dim3(2, NB * NHEAD), 256, ATTN_SMEM>>>(q2h, q2l, k2h, k2l,
        vth, vtl, mask, aoh, aol);

    // output projection
    {
        GemmGroup g = {};
        g.base1 = 256; g.base2 = 256;
        g.gx[0] = 4; g.Ah[0] = aoh; g.Al[0] = aol; g.Bh[0] = pwh; g.Bl[0] = pwl;
        g.C[0] = out; g.bias[0] = proj_b; g.lda[0] = CDIM; g.N[0] = CDIM; g.K[0] = CDIM;
        gemm3g_kernel<2><<<256, 256, SM2>>>(g);
    }
}